// round 2
// baseline (speedup 1.0000x reference)
#include <cuda_runtime.h>
#include <math.h>

// ---------------- problem constants ----------------
#define BSZ    128
#define DIN    512
#define DMODEL 2048
#define MEMN   25
#define HIDN   32
#define NSY    256
#define NSYNC  32896        // 256*257/2
#define OUTD   1000
#define NITER  24
#define DK     (DIN + DMODEL)   // 2560
#define N1     (2 * DMODEL)     // 4096
#define SPLITK 16
#define KCHUNK (NSYNC / SPLITK) // 2056, divisible by 8
#define PRED_OFF 0
#define CERT_OFF (BSZ * OUTD * NITER)

// ---------------- persistent scratch (device globals, no allocs) ----------------
__device__ float g_trace[BSZ * DMODEL * MEMN];   // [b][d][m] circular, 26.2 MB
__device__ float g_actT [DMODEL * BSZ];          // [d][b] column-major activations
__device__ float g_z    [BSZ * N1];              // synapse pre-GLU output
__device__ float g_alpha[NSYNC * BSZ];           // [p][b]
__device__ float g_sync [NSYNC * BSZ];           // [p][b]
__device__ float g_r    [NSYNC];
__device__ int   g_pi   [NSYNC];
__device__ int   g_pj   [NSYNC];
__device__ float g_partial[SPLITK * BSZ * OUTD]; // split-K partials

__device__ __forceinline__ float sigmoidf_(float x) {
    return 1.0f / (1.0f + expf(-x));
}

// ---------------- init kernels (run every launch; deterministic) ----------------
__global__ void k_init_pairs(const float* __restrict__ decay) {
    int p = blockIdx.x * 256 + threadIdx.x;
    if (p >= NSYNC) return;
    // invert S(i) = i*NSY - i*(i-1)/2  (row starts of triu incl. diagonal)
    float pf = (float)p;
    int i = (int)floorf(256.5f - sqrtf(256.5f * 256.5f - 2.0f * pf));
    if (i < 0) i = 0;
    if (i > NSY - 1) i = NSY - 1;
    while (i > 0 && (i * NSY - i * (i - 1) / 2) > p) i--;
    while (i < NSY - 1 && ((i + 1) * NSY - (i + 1) * i / 2) <= p) i++;
    int Si = i * NSY - i * (i - 1) / 2;
    g_pi[p] = i;
    g_pj[p] = i + (p - Si);
    float d = fminf(fmaxf(decay[p], 0.0f), 15.0f);
    g_r[p] = expf(-d);
}

__global__ void k_init_trace(const float* __restrict__ st) {
    int idx = blockIdx.x * 256 + threadIdx.x;
    if (idx >= BSZ * DMODEL * MEMN) return;
    int m = idx % MEMN;
    int d = (idx / MEMN) % DMODEL;
    g_trace[idx] = st[d * MEMN + m];
}

__global__ void k_init_act(const float* __restrict__ sas) {
    int idx = blockIdx.x * 256 + threadIdx.x;
    if (idx >= DMODEL * BSZ) return;
    g_actT[idx] = sas[idx >> 7];   // [d][b], b = low 7 bits
}

__global__ void k_init_alpha(const float* __restrict__ sas,
                             const int* __restrict__ il,
                             const int* __restrict__ ir) {
    int p = blockIdx.x;
    int b = threadIdx.x;
    float v = sas[il[g_pi[p]]] * sas[ir[g_pj[p]]];
    g_alpha[p * BSZ + b] = v;
}

// ---------------- K1: synapse GEMM  z = [x|act] @ syn_w + syn_b ----------------
// M=128, K=2560, N=4096. BM=BN=64, BK=8, 256 thr, 4x4 thread tile.
__global__ __launch_bounds__(256) void k_gemm1(const float* __restrict__ x,
                                               const float* __restrict__ syn_w,
                                               const float* __restrict__ syn_b) {
    __shared__ float As[8][64];
    __shared__ float Bs[8][64];
    int n0 = blockIdx.x * 64;
    int m0 = blockIdx.y * 64;
    int tid = threadIdx.x;
    int tx = tid & 15, ty = tid >> 4;
    float acc[4][4] = {};
    int ml = tid & 63;
    int kq = tid >> 6;   // 0..3
    for (int k0 = 0; k0 < DK; k0 += 8) {
#pragma unroll
        for (int u = 0; u < 2; u++) {
            int kk = kq + u * 4;
            int k = k0 + kk;
            int gm = m0 + ml;
            float v;
            if (k < DIN) v = x[gm * DIN + k];
            else         v = g_actT[(k - DIN) * BSZ + gm];
            As[kk][ml] = v;
            Bs[kk][ml] = syn_w[k * N1 + n0 + ml];
        }
        __syncthreads();
#pragma unroll
        for (int kk = 0; kk < 8; kk++) {
            float a[4], b[4];
#pragma unroll
            for (int i = 0; i < 4; i++) a[i] = As[kk][ty * 4 + i];
#pragma unroll
            for (int j = 0; j < 4; j++) b[j] = Bs[kk][tx * 4 + j];
#pragma unroll
            for (int i = 0; i < 4; i++)
#pragma unroll
                for (int j = 0; j < 4; j++) acc[i][j] += a[i] * b[j];
        }
        __syncthreads();
    }
#pragma unroll
    for (int i = 0; i < 4; i++)
#pragma unroll
        for (int j = 0; j < 4; j++) {
            int gn = n0 + tx * 4 + j;
            g_z[(m0 + ty * 4 + i) * N1 + gn] = acc[i][j] + syn_b[gn];
        }
}

// ---------------- K2: GLU + LayerNorm -> write into trace slot ----------------
__global__ __launch_bounds__(256) void k_glu_ln(const float* __restrict__ ln_g,
                                                const float* __restrict__ ln_b,
                                                int slot) {
    int b = blockIdx.x;
    int tid = threadIdx.x;
    __shared__ float sv[DMODEL];
    __shared__ float red[256];
    float s1 = 0.f, s2 = 0.f;
    for (int d = tid; d < DMODEL; d += 256) {
        float a  = g_z[b * N1 + d];
        float bb = g_z[b * N1 + DMODEL + d];
        float v = a * sigmoidf_(bb);
        sv[d] = v;
        s1 += v;
        s2 += v * v;
    }
    red[tid] = s1; __syncthreads();
    for (int s = 128; s > 0; s >>= 1) { if (tid < s) red[tid] += red[tid + s]; __syncthreads(); }
    float mu = red[0] / (float)DMODEL;
    __syncthreads();
    red[tid] = s2; __syncthreads();
    for (int s = 128; s > 0; s >>= 1) { if (tid < s) red[tid] += red[tid + s]; __syncthreads(); }
    float var = red[0] / (float)DMODEL - mu * mu;
    float inv = rsqrtf(var + 1e-5f);
    for (int d = tid; d < DMODEL; d += 256) {
        float st = (sv[d] - mu) * inv * ln_g[d] + ln_b[d];
        g_trace[(b * DMODEL + d) * MEMN + slot] = st;
    }
}

// ---------------- K3: trace_proc (per-d MLP over MEM) -> act ----------------
__global__ __launch_bounds__(128) void k_traceproc(const float* __restrict__ w1,
                                                   const float* __restrict__ b1,
                                                   const float* __restrict__ w2,
                                                   const float* __restrict__ b2,
                                                   int t) {
    int d = blockIdx.x;
    int b = threadIdx.x;   // 128 threads = batch
    __shared__ float w1s[MEMN][64];
    __shared__ float b1s[64];
    __shared__ float w2s[32][2];
    __shared__ float b2s[2];
    for (int idx = b; idx < MEMN * 64; idx += 128) {
        int m = idx / 64, h = idx % 64;
        w1s[m][h] = w1[(m * 64 + h) * DMODEL + d];
    }
    if (b < 64) b1s[b] = b1[d * 64 + b];
    if (b < 64) { int h = b >> 1, o = b & 1; w2s[h][o] = w2[(h * 2 + o) * DMODEL + d]; }
    if (b < 2)  b2s[b] = b2[d * 2 + b];
    __syncthreads();

    float tr[MEMN];
    const float* tp = &g_trace[(b * DMODEL + d) * MEMN];
    int base = (t + 1) % MEMN;
#pragma unroll
    for (int m = 0; m < MEMN; m++) {
        int ph = base + m;
        if (ph >= MEMN) ph -= MEMN;
        tr[m] = tp[ph];
    }
    float o0 = b2s[0], o1 = b2s[1];
#pragma unroll
    for (int hh = 0; hh < 32; hh++) {
        float pa = b1s[hh], pb = b1s[hh + 32];
#pragma unroll
        for (int m = 0; m < MEMN; m++) {
            pa += tr[m] * w1s[m][hh];
            pb += tr[m] * w1s[m][hh + 32];
        }
        float h = pa * sigmoidf_(pb);
        o0 += h * w2s[hh][0];
        o1 += h * w2s[hh][1];
    }
    g_actT[d * BSZ + b] = o0 * sigmoidf_(o1);
}

// ---------------- K4: pairwise + alpha update + sync ----------------
__global__ __launch_bounds__(256) void k_syncpair(const int* __restrict__ il,
                                                  const int* __restrict__ ir,
                                                  int t) {
    int p = blockIdx.x * 2 + threadIdx.y;
    int b = threadIdx.x;
    int i = g_pi[p], j = g_pj[p];
    float l  = g_actT[il[i] * BSZ + b];
    float rr = g_actT[ir[j] * BSZ + b];
    float r = g_r[p];
    float a = g_alpha[p * BSZ + b];
    a = r * a + l * rr;
    g_alpha[p * BSZ + b] = a;
    float beta = 1.0f;
    for (int k = 0; k <= t; k++) beta = r * beta + 1.0f;
    g_sync[p * BSZ + b] = a / sqrtf(beta);
}

// ---------------- K5: output GEMM (split-K) ----------------
// pred = sync[128 x 32896] @ out_w[32896 x 1000]; sync stored [p][b].
__global__ __launch_bounds__(256) void k_gemm2(const float* __restrict__ W) {
    __shared__ float As[8][64];
    __shared__ float Bs[8][64];
    int n0 = blockIdx.x * 64;
    int m0 = blockIdx.y * 64;
    int kbeg = blockIdx.z * KCHUNK;
    int tid = threadIdx.x;
    int tx = tid & 15, ty = tid >> 4;
    float acc[4][4] = {};
    int ml = tid & 63;
    int kq = tid >> 6;
    for (int k0 = 0; k0 < KCHUNK; k0 += 8) {
#pragma unroll
        for (int u = 0; u < 2; u++) {
            int kk = kq + u * 4;
            int k = kbeg + k0 + kk;
            As[kk][ml] = g_sync[k * BSZ + m0 + ml];
            int gn = n0 + ml;
            Bs[kk][ml] = (gn < OUTD) ? W[k * OUTD + gn] : 0.0f;
        }
        __syncthreads();
#pragma unroll
        for (int kk = 0; kk < 8; kk++) {
            float a[4], b[4];
#pragma unroll
            for (int i = 0; i < 4; i++) a[i] = As[kk][ty * 4 + i];
#pragma unroll
            for (int j = 0; j < 4; j++) b[j] = Bs[kk][tx * 4 + j];
#pragma unroll
            for (int i = 0; i < 4; i++)
#pragma unroll
                for (int j = 0; j < 4; j++) acc[i][j] += a[i] * b[j];
        }
        __syncthreads();
    }
#pragma unroll
    for (int i = 0; i < 4; i++)
#pragma unroll
        for (int j = 0; j < 4; j++) {
            int gn = n0 + tx * 4 + j;
            if (gn < OUTD)
                g_partial[(blockIdx.z * BSZ + m0 + ty * 4 + i) * OUTD + gn] = acc[i][j];
        }
}

// ---------------- K6: split-K reduce + bias + write preds + entropy ----------------
__global__ __launch_bounds__(256) void k_finish(const float* __restrict__ outb,
                                                float* __restrict__ dout,
                                                int t) {
    int b = blockIdx.x;
    int tid = threadIdx.x;
    __shared__ float sp[OUTD];
    __shared__ float red[256];
    for (int n = tid; n < OUTD; n += 256) {
        float v = outb[n];
#pragma unroll
        for (int s = 0; s < SPLITK; s++) v += g_partial[(s * BSZ + b) * OUTD + n];
        sp[n] = v;
        dout[PRED_OFF + (b * OUTD + n) * NITER + t] = v;
    }
    __syncthreads();
    // max
    float mx = -3.4e38f;
    for (int n = tid; n < OUTD; n += 256) mx = fmaxf(mx, sp[n]);
    red[tid] = mx; __syncthreads();
    for (int s = 128; s > 0; s >>= 1) { if (tid < s) red[tid] = fmaxf(red[tid], red[tid + s]); __syncthreads(); }
    float smax = red[0];
    __syncthreads();
    // sum exp
    float se = 0.f;
    for (int n = tid; n < OUTD; n += 256) se += expf(sp[n] - smax);
    red[tid] = se; __syncthreads();
    for (int s = 128; s > 0; s >>= 1) { if (tid < s) red[tid] += red[tid + s]; __syncthreads(); }
    float lse = smax + logf(red[0]);
    __syncthreads();
    // entropy
    float ent = 0.f;
    for (int n = tid; n < OUTD; n += 256) {
        float lp = sp[n] - lse;
        ent += expf(lp) * lp;
    }
    red[tid] = ent; __syncthreads();
    for (int s = 128; s > 0; s >>= 1) { if (tid < s) red[tid] += red[tid + s]; __syncthreads(); }
    if (tid == 0) {
        float ne = -red[0] / logf(1000.0f);
        dout[CERT_OFF + (b * 2 + 0) * NITER + t] = ne;
        dout[CERT_OFF + (b * 2 + 1) * NITER + t] = 1.0f - ne;
    }
}

// ---------------- host ----------------
extern "C" void kernel_launch(void* const* d_in, const int* in_sizes, int n_in,
                              void* d_out, int out_size) {
    const float* x      = (const float*)d_in[0];
    const float* syn_w  = (const float*)d_in[1];
    const float* syn_b  = (const float*)d_in[2];
    const float* ln_g   = (const float*)d_in[3];
    const float* ln_b   = (const float*)d_in[4];
    const float* tp_w1  = (const float*)d_in[5];
    const float* tp_b1  = (const float*)d_in[6];
    const float* tp_w2  = (const float*)d_in[7];
    const float* tp_b2  = (const float*)d_in[8];
    const float* sas    = (const float*)d_in[9];
    const float* strc   = (const float*)d_in[10];
    const float* decay  = (const float*)d_in[11];
    const float* out_w  = (const float*)d_in[12];
    const float* out_b  = (const float*)d_in[13];
    const int*   il     = (const int*)d_in[14];
    const int*   ir     = (const int*)d_in[15];
    float* out = (float*)d_out;

    k_init_pairs<<<(NSYNC + 255) / 256, 256>>>(decay);
    k_init_trace<<<(BSZ * DMODEL * MEMN + 255) / 256, 256>>>(strc);
    k_init_act<<<(DMODEL * BSZ) / 256, 256>>>(sas);
    k_init_alpha<<<NSYNC, BSZ>>>(sas, il, ir);

    for (int t = 0; t < NITER; t++) {
        k_gemm1<<<dim3(N1 / 64, BSZ / 64), 256>>>(x, syn_w, syn_b);
        k_glu_ln<<<BSZ, 256>>>(ln_g, ln_b, t % MEMN);
        k_traceproc<<<DMODEL, BSZ>>>(tp_w1, tp_b1, tp_w2, tp_b2, t);
        k_syncpair<<<NSYNC / 2, dim3(BSZ, 2)>>>(il, ir, t);
        k_gemm2<<<dim3(16, 2, SPLITK), 256>>>(out_w);
        k_finish<<<BSZ, 256>>>(out_b, out, t);
    }
}

// round 4
// speedup vs baseline: 1.2139x; 1.2139x over previous
#include <cuda_runtime.h>
#include <math.h>

#define BSZ    128
#define DIN    512
#define DMODEL 2048
#define MEMN   25
#define NSY    256
#define NSYNC  32896
#define OUTD   1000
#define NITER  24
#define N1     4096
#define SK1    4
#define SK2    18
#define CERT_OFF (BSZ * OUTD * NITER)

typedef unsigned long long ULL;

__device__ float g_trace[MEMN * DMODEL * BSZ];
__device__ float g_actT [DMODEL * BSZ];
__device__ float g_xT   [DIN * BSZ];
__device__ float g_z0   [BSZ * N1];
__device__ float g_zp   [SK1 * BSZ * N1];
__device__ float g_alpha[NSYNC * BSZ];
__device__ float g_sync [NSYNC * BSZ];
__device__ float g_r    [NSYNC];
__device__ int   g_pi   [NSYNC];
__device__ int   g_pj   [NSYNC];
__device__ float g_part [SK2 * BSZ * OUTD];
__device__ float g_w1i  [DMODEL * MEMN * 64];
__device__ float g_w2T  [DMODEL * 64];

__device__ __forceinline__ float sigmoidf_(float x) { return 1.0f / (1.0f + expf(-x)); }
__device__ __forceinline__ ULL dup2(float x) {
    ULL r; unsigned u = __float_as_uint(x);
    asm("mov.b64 %0, {%1, %1};" : "=l"(r) : "r"(u)); return r;
}
__device__ __forceinline__ ULL pack2(float lo, float hi) {
    ULL r; asm("mov.b64 %0, {%1, %2};" : "=l"(r) : "r"(__float_as_uint(lo)), "r"(__float_as_uint(hi)));
    return r;
}
__device__ __forceinline__ void fma2(ULL& d, ULL a, ULL b) {
    asm("fma.rn.f32x2 %0, %1, %2, %3;" : "=l"(d) : "l"(a), "l"(b), "l"(d));
}
__device__ __forceinline__ float lo32(ULL v) { return __uint_as_float((unsigned)v); }
__device__ __forceinline__ float hi32(ULL v) { return __uint_as_float((unsigned)(v >> 32)); }

// ---------------- init ----------------
__global__ void k_init_xT(const float* __restrict__ x) {
    int idx = blockIdx.x * 256 + threadIdx.x;
    if (idx >= DIN * BSZ) return;
    g_xT[idx] = x[(idx & 127) * DIN + (idx >> 7)];
}

__global__ void k_init_trace_act(const float* __restrict__ strc, const float* __restrict__ sas) {
    int idx = blockIdx.x * 256 + threadIdx.x;
    if (idx < MEMN * DMODEL * BSZ) {
        int d = (idx >> 7) & (DMODEL - 1);
        int m = idx >> 18;
        g_trace[idx] = strc[d * MEMN + m];
        return;
    }
    int j = idx - MEMN * DMODEL * BSZ;
    if (j < DMODEL * BSZ) g_actT[j] = sas[j >> 7];
}

__global__ void k_init_w(const float* __restrict__ w1, const float* __restrict__ w2) {
    int idx = blockIdx.x * 256 + threadIdx.x;
    if (idx < MEMN * 64 * DMODEL) {
        int d = idx & (DMODEL - 1);
        int rem = idx >> 11;
        int h = rem & 63, m = rem >> 6;
        g_w1i[((d * MEMN + m) * 32 + (h & 31)) * 2 + (h >> 5)] = w1[idx];
        return;
    }
    int j = idx - MEMN * 64 * DMODEL;
    if (j < 64 * DMODEL) g_w2T[(j & (DMODEL - 1)) * 64 + (j >> 11)] = w2[j];
}

__global__ void k_init_alpha(const float* __restrict__ sas, const float* __restrict__ decay,
                             const int* __restrict__ il, const int* __restrict__ ir) {
    int p = blockIdx.x, b = threadIdx.x;
    float pf = (float)p;
    int i = (int)floorf(256.5f - sqrtf(256.5f * 256.5f - 2.0f * pf));
    if (i < 0) i = 0;
    if (i > NSY - 1) i = NSY - 1;
    while (i > 0 && (i * NSY - i * (i - 1) / 2) > p) i--;
    while (i < NSY - 1 && ((i + 1) * NSY - (i + 1) * i / 2) <= p) i++;
    int j = i + (p - (i * NSY - i * (i - 1) / 2));
    if (b == 0) {
        g_pi[p] = i; g_pj[p] = j;
        g_r[p] = expf(-fminf(fmaxf(decay[p], 0.0f), 15.0f));
    }
    g_alpha[p * BSZ + b] = sas[il[i]] * sas[ir[j]];
}

// ---------------- FMA2 GEMM: C[z] = A[K][128]^T @ B[K][ldb] ----------------
// 128x128 tile, 256 threads, 8m x 8n(packed ULL x4) per thread.
__global__ __launch_bounds__(256) void k_gemm_f2(
    const float* __restrict__ A, const float* __restrict__ B,
    int ldb, int Nmax, int nkb, int SK, float* __restrict__ C, int ldc)
{
    __shared__ float As[2][8][128];
    __shared__ float Bs[2][8][128];
    int n0 = blockIdx.x * 128;
    int z  = blockIdx.y;
    int kb0 = z * nkb / SK, kb1 = (z + 1) * nkb / SK;
    int tid = threadIdx.x;
    int lr = tid >> 5, lc = (tid & 31) * 4;
    int ty = tid >> 4, tx = tid & 15;
    bool fastB = (n0 + 128 <= Nmax);

    ULL acc[8][4];
#pragma unroll
    for (int i = 0; i < 8; i++)
#pragma unroll
        for (int j = 0; j < 4; j++) acc[i][j] = 0ULL;

    float4 pa, pb;
    {
        int krow = kb0 * 8 + lr;
        pa = *(const float4*)(A + krow * BSZ + lc);
        if (fastB) pb = *(const float4*)(B + (size_t)krow * ldb + n0 + lc);
        else {
            float t[4];
#pragma unroll
            for (int u = 0; u < 4; u++) {
                int col = n0 + lc + u;
                t[u] = (col < Nmax) ? B[(size_t)krow * ldb + col] : 0.0f;
            }
            pb = make_float4(t[0], t[1], t[2], t[3]);
        }
    }
    *(float4*)&As[0][lr][lc] = pa;
    *(float4*)&Bs[0][lr][lc] = pb;
    __syncthreads();

    int buf = 0;
    for (int kb = kb0; kb < kb1; kb++) {
        bool has = (kb + 1 < kb1);
        if (has) {
            int krow = (kb + 1) * 8 + lr;
            pa = *(const float4*)(A + krow * BSZ + lc);
            if (fastB) pb = *(const float4*)(B + (size_t)krow * ldb + n0 + lc);
            else {
                float t[4];
#pragma unroll
                for (int u = 0; u < 4; u++) {
                    int col = n0 + lc + u;
                    t[u] = (col < Nmax) ? B[(size_t)krow * ldb + col] : 0.0f;
                }
                pb = make_float4(t[0], t[1], t[2], t[3]);
            }
        }
#pragma unroll
        for (int kk = 0; kk < 8; kk++) {
            float a[8];
            *(float4*)&a[0] = *(const float4*)&As[buf][kk][ty * 8];
            *(float4*)&a[4] = *(const float4*)&As[buf][kk][ty * 8 + 4];
            ULL bv[4];
            const ULL* bp = (const ULL*)&Bs[buf][kk][tx * 8];
#pragma unroll
            for (int j = 0; j < 4; j++) bv[j] = bp[j];
#pragma unroll
            for (int i = 0; i < 8; i++) {
                ULL ad = dup2(a[i]);
#pragma unroll
                for (int j = 0; j < 4; j++) fma2(acc[i][j], ad, bv[j]);
            }
        }
        if (has) {
            *(float4*)&As[buf ^ 1][lr][lc] = pa;
            *(float4*)&Bs[buf ^ 1][lr][lc] = pb;
            __syncthreads();
            buf ^= 1;
        }
    }

    float* Cz = C + (size_t)z * BSZ * ldc;
#pragma unroll
    for (int i = 0; i < 8; i++) {
        int m = ty * 8 + i;
#pragma unroll
        for (int j = 0; j < 4; j++) {
            int n = n0 + tx * 8 + 2 * j;
            if (n < Nmax)     Cz[(size_t)m * ldc + n]     = lo32(acc[i][j]);
            if (n + 1 < Nmax) Cz[(size_t)m * ldc + n + 1] = hi32(acc[i][j]);
        }
    }
}

// ---------------- GLU + LayerNorm -> trace slot ----------------
__global__ __launch_bounds__(256) void k_glu_ln(const float* __restrict__ syn_b,
                                                const float* __restrict__ ln_g,
                                                const float* __restrict__ ln_b, int slot) {
    int b = blockIdx.x, tid = threadIdx.x;
    __shared__ float sv[DMODEL];
    __shared__ float red[256];
    float s1 = 0.f, s2 = 0.f;
    for (int d = tid; d < DMODEL; d += 256) {
        float za = syn_b[d] + g_z0[b * N1 + d];
        float zb = syn_b[d + DMODEL] + g_z0[b * N1 + DMODEL + d];
#pragma unroll
        for (int s = 0; s < SK1; s++) {
            za += g_zp[(s * BSZ + b) * N1 + d];
            zb += g_zp[(s * BSZ + b) * N1 + DMODEL + d];
        }
        float v = za * sigmoidf_(zb);
        sv[d] = v; s1 += v; s2 += v * v;
    }
    red[tid] = s1; __syncthreads();
    for (int s = 128; s > 0; s >>= 1) { if (tid < s) red[tid] += red[tid + s]; __syncthreads(); }
    float mu = red[0] / (float)DMODEL;
    __syncthreads();
    red[tid] = s2; __syncthreads();
    for (int s = 128; s > 0; s >>= 1) { if (tid < s) red[tid] += red[tid + s]; __syncthreads(); }
    float inv = rsqrtf(red[0] / (float)DMODEL - mu * mu + 1e-5f);
    for (int d = tid; d < DMODEL; d += 256)
        g_trace[(slot * DMODEL + d) * BSZ + b] = (sv[d] - mu) * inv * ln_g[d] + ln_b[d];
}

// ---------------- trace_proc ----------------
__global__ __launch_bounds__(128) void k_traceproc(const float* __restrict__ b1,
                                                   const float* __restrict__ b2, int t) {
    int d = blockIdx.x, b = threadIdx.x;
    __shared__ float ws[MEMN * 64];
    const float* src = g_w1i + d * (MEMN * 64);
    for (int i = b; i < MEMN * 64; i += 128) ws[i] = src[i];
    __syncthreads();

    ULL trp[MEMN];
    int base = (t + 1) % MEMN;
#pragma unroll
    for (int m = 0; m < MEMN; m++) {
        int pm = base + m; if (pm >= MEMN) pm -= MEMN;
        trp[m] = dup2(g_trace[(pm * DMODEL + d) * BSZ + b]);
    }
    const float* b1d = b1 + d * 64;
    const float* w2d = g_w2T + d * 64;
    float o0 = b2[d * 2], o1 = b2[d * 2 + 1];
#pragma unroll
    for (int h2 = 0; h2 < 32; h2 += 2) {
        ULL acc0 = pack2(b1d[h2],     b1d[h2 + 32]);
        ULL acc1 = pack2(b1d[h2 + 1], b1d[h2 + 33]);
        const ULL* wp = ((const ULL*)ws) + h2;
#pragma unroll
        for (int m = 0; m < MEMN; m++) {
            fma2(acc0, trp[m], wp[m * 32]);
            fma2(acc1, trp[m], wp[m * 32 + 1]);
        }
        float h0 = lo32(acc0) * sigmoidf_(hi32(acc0));
        float h1 = lo32(acc1) * sigmoidf_(hi32(acc1));
        o0 += h0 * w2d[h2 * 2]     + h1 * w2d[(h2 + 1) * 2];
        o1 += h0 * w2d[h2 * 2 + 1] + h1 * w2d[(h2 + 1) * 2 + 1];
    }
    g_actT[d * BSZ + b] = o0 * sigmoidf_(o1);
}

// ---------------- pairwise + alpha + sync ----------------
__global__ __launch_bounds__(256) void k_syncpair(const int* __restrict__ il,
                                                  const int* __restrict__ ir, int t) {
    int p = blockIdx.x * 2 + threadIdx.y;
    int b = threadIdx.x;
    float l  = g_actT[il[g_pi[p]] * BSZ + b];
    float rr = g_actT[ir[g_pj[p]] * BSZ + b];
    float r = g_r[p];
    float a = r * g_alpha[p * BSZ + b] + l * rr;
    g_alpha[p * BSZ + b] = a;
    float beta = 1.0f;
    for (int k = 0; k <= t; k++) beta = r * beta + 1.0f;
    g_sync[p * BSZ + b] = a / sqrtf(beta);
}

// ---------------- reduce + bias + preds + entropy ----------------
__global__ __launch_bounds__(256) void k_finish(const float* __restrict__ outb,
                                                float* __restrict__ dout, int t) {
    int b = blockIdx.x, tid = threadIdx.x;
    __shared__ float sp[OUTD];
    __shared__ float red[256];
    for (int n = tid; n < OUTD; n += 256) {
        float v = outb[n];
#pragma unroll
        for (int s = 0; s < SK2; s++) v += g_part[(s * BSZ + b) * OUTD + n];
        sp[n] = v;
        dout[(b * OUTD + n) * NITER + t] = v;
    }
    __syncthreads();
    float mx = -3.4e38f;
    for (int n = tid; n < OUTD; n += 256) mx = fmaxf(mx, sp[n]);
    red[tid] = mx; __syncthreads();
    for (int s = 128; s > 0; s >>= 1) { if (tid < s) red[tid] = fmaxf(red[tid], red[tid + s]); __syncthreads(); }
    float smax = red[0];
    __syncthreads();
    float se = 0.f;
    for (int n = tid; n < OUTD; n += 256) se += expf(sp[n] - smax);
    red[tid] = se; __syncthreads();
    for (int s = 128; s > 0; s >>= 1) { if (tid < s) red[tid] += red[tid + s]; __syncthreads(); }
    float lse = smax + logf(red[0]);
    __syncthreads();
    float ent = 0.f;
    for (int n = tid; n < OUTD; n += 256) { float lp = sp[n] - lse; ent += expf(lp) * lp; }
    red[tid] = ent; __syncthreads();
    for (int s = 128; s > 0; s >>= 1) { if (tid < s) red[tid] += red[tid + s]; __syncthreads(); }
    if (tid == 0) {
        float ne = -red[0] / logf(1000.0f);
        dout[CERT_OFF + (b * 2 + 0) * NITER + t] = ne;
        dout[CERT_OFF + (b * 2 + 1) * NITER + t] = 1.0f - ne;
    }
}

// ---------------- host ----------------
extern "C" void kernel_launch(void* const* d_in, const int* in_sizes, int n_in,
                              void* d_out, int out_size) {
    const float* x      = (const float*)d_in[0];
    const float* syn_w  = (const float*)d_in[1];
    const float* syn_b  = (const float*)d_in[2];
    const float* ln_g   = (const float*)d_in[3];
    const float* ln_b   = (const float*)d_in[4];
    const float* tp_b1  = (const float*)d_in[6];
    const float* tp_b2  = (const float*)d_in[8];
    const float* sas    = (const float*)d_in[9];
    const float* strc   = (const float*)d_in[10];
    const float* decay  = (const float*)d_in[11];
    const float* out_w  = (const float*)d_in[12];
    const float* out_b  = (const float*)d_in[13];
    const int*   il     = (const int*)d_in[14];
    const int*   ir     = (const int*)d_in[15];
    const float* tp_w1  = (const float*)d_in[5];
    const float* tp_w2  = (const float*)d_in[7];
    float* out = (float*)d_out;

    // Real device addresses of __device__ globals (host-side symbol names are
    // shadow objects — passing them as kernel args was round-3's bug).
    float *p_xT, *p_actT, *p_sync, *p_z0, *p_zp, *p_part;
    cudaGetSymbolAddress((void**)&p_xT,   g_xT);
    cudaGetSymbolAddress((void**)&p_actT, g_actT);
    cudaGetSymbolAddress((void**)&p_sync, g_sync);
    cudaGetSymbolAddress((void**)&p_z0,   g_z0);
    cudaGetSymbolAddress((void**)&p_zp,   g_zp);
    cudaGetSymbolAddress((void**)&p_part, g_part);

    k_init_xT<<<(DIN * BSZ + 255) / 256, 256>>>(x);
    k_init_trace_act<<<(MEMN * DMODEL * BSZ + DMODEL * BSZ + 255) / 256, 256>>>(strc, sas);
    k_init_w<<<(MEMN * 64 * DMODEL + 64 * DMODEL + 255) / 256, 256>>>(tp_w1, tp_w2);
    k_init_alpha<<<NSYNC, BSZ>>>(sas, decay, il, ir);
    // z0 = x @ W_top (one-time), K=512 -> 64 k-blocks, SK=1
    k_gemm_f2<<<dim3(N1 / 128, 1), 256>>>(p_xT, syn_w, N1, N1, DIN / 8, 1, p_z0, N1);

    for (int t = 0; t < NITER; t++) {
        // gemm1: act part, K=2048
        k_gemm_f2<<<dim3(N1 / 128, SK1), 256>>>(p_actT, syn_w + (size_t)DIN * N1, N1, N1,
                                                DMODEL / 8, SK1, p_zp, N1);
        k_glu_ln<<<BSZ, 256>>>(syn_b, ln_g, ln_b, t % MEMN);
        k_traceproc<<<DMODEL, BSZ>>>(tp_b1, tp_b2, t);
        k_syncpair<<<NSYNC / 2, dim3(BSZ, 2)>>>(il, ir, t);
        // gemm2: K=32896 -> 4112 k-blocks, 8 n-blocks, SK2 splits
        k_gemm_f2<<<dim3(8, SK2), 256>>>(p_sync, out_w, OUTD, OUTD,
                                         NSYNC / 8, SK2, p_part, OUTD);
        k_finish<<<BSZ, 256>>>(out_b, out, t);
    }
}

// round 6
// speedup vs baseline: 2.2509x; 1.8544x over previous
#include <cuda_runtime.h>
#include <cuda_bf16.h>
#include <math.h>

#define BSZ    128
#define DIN    512
#define DMODEL 2048
#define MEMN   25
#define NSY    256
#define NSYNC  32896
#define OUTD   1000
#define OUTPAD 1024
#define NITER  24
#define N1     4096
#define SK1    4
#define SK2    18
#define CERT_OFF (BSZ * OUTD * NITER)

// init ranges
#define R1 (DIN * BSZ)
#define R2 (MEMN * DMODEL * BSZ)
#define R3 (DMODEL * BSZ)
#define R4 (MEMN * 64 * DMODEL)
#define R5 (64 * DMODEL)
#define RTOT (R1 + R2 + R3 + R4 + R5)

typedef unsigned long long ULL;
typedef unsigned U32;

// ---------------- persistent scratch ----------------
__device__ float g_trace[MEMN * DMODEL * BSZ];
__device__ float g_actT [DMODEL * BSZ];            // fp32 [d][b] for pairwise gather
__device__ U32   g_actH2[DMODEL / 2 * BSZ];        // bf16-hi pairs: u32[k2][m] = (k even | k odd<<16)
__device__ U32   g_actL2[DMODEL / 2 * BSZ];        // bf16-lo pairs
__device__ U32   g_syncH2[NSYNC / 2 * BSZ];
__device__ U32   g_syncL2[NSYNC / 2 * BSZ];
__device__ float g_xT   [DIN * BSZ];
__device__ float g_z0   [BSZ * N1];
__device__ float g_zp   [SK1 * BSZ * N1];
__device__ float g_alpha[NSYNC * BSZ];
__device__ float g_r    [NSYNC];
__device__ int   g_pi   [NSYNC];
__device__ int   g_pj   [NSYNC];
__device__ float g_part [SK2 * BSZ * OUTD];
__device__ float g_w1i  [DMODEL * MEMN * 64];
__device__ float g_w2T  [DMODEL * 64];
__device__ __nv_bfloat16 g_synTh[(size_t)N1 * DMODEL];      // [n][k]
__device__ __nv_bfloat16 g_synTl[(size_t)N1 * DMODEL];
__device__ __nv_bfloat16 g_outTh[(size_t)OUTPAD * NSYNC];   // [n][k], rows >= OUTD zero
__device__ __nv_bfloat16 g_outTl[(size_t)OUTPAD * NSYNC];

__device__ __forceinline__ float sigmoidf_(float x) { return 1.0f / (1.0f + expf(-x)); }
__device__ __forceinline__ ULL dup2(float x) {
    ULL r; unsigned u = __float_as_uint(x);
    asm("mov.b64 %0, {%1, %1};" : "=l"(r) : "r"(u)); return r;
}
__device__ __forceinline__ ULL pack2(float lo, float hi) {
    ULL r; asm("mov.b64 %0, {%1, %2};" : "=l"(r) : "r"(__float_as_uint(lo)), "r"(__float_as_uint(hi)));
    return r;
}
__device__ __forceinline__ void fma2(ULL& d, ULL a, ULL b) {
    asm("fma.rn.f32x2 %0, %1, %2, %3;" : "=l"(d) : "l"(a), "l"(b), "l"(d));
}
__device__ __forceinline__ float lo32(ULL v) { return __uint_as_float((unsigned)v); }
__device__ __forceinline__ float hi32(ULL v) { return __uint_as_float((unsigned)(v >> 32)); }

// split v into bf16 hi + bf16 lo(correction), store into the paired [k2][m] layout
__device__ __forceinline__ void hl_store(float v, int k, int m,
                                         U32* __restrict__ H2, U32* __restrict__ L2) {
    __nv_bfloat16 h = __float2bfloat16(v);
    __nv_bfloat16 l = __float2bfloat16(v - __bfloat162float(h));
    __nv_bfloat16* ph = (__nv_bfloat16*)H2;
    __nv_bfloat16* pl = (__nv_bfloat16*)L2;
    int idx = (k >> 1) * (2 * BSZ) + m * 2 + (k & 1);
    ph[idx] = h;
    pl[idx] = l;
}

// ---------------- m16n8k16 bf16 MMA ----------------
__device__ __forceinline__ void mma16816(float* c, const U32* a, U32 b0, U32 b1) {
    asm volatile("mma.sync.aligned.m16n8k16.row.col.f32.bf16.bf16.f32 "
                 "{%0,%1,%2,%3}, {%4,%5,%6,%7}, {%8,%9}, {%0,%1,%2,%3};"
                 : "+f"(c[0]), "+f"(c[1]), "+f"(c[2]), "+f"(c[3])
                 : "r"(a[0]), "r"(a[1]), "r"(a[2]), "r"(a[3]), "r"(b0), "r"(b1));
}

// ================= HMMA GEMM =================
// C[z][128][ldc] = split-K partial of A(fp32 via bf16 hi/lo [k2][128] u32 pairs) @ B([n][k] bf16 hi/lo)
// grid: (N/128, SK); block 256 = 8 warps (4m x 2n), warp tile 32m x 64n.
__global__ __launch_bounds__(256) void k_gemm_mma(
    const U32* __restrict__ AH2, const U32* __restrict__ AL2,
    const __nv_bfloat16* __restrict__ Bh, const __nv_bfloat16* __restrict__ Bl,
    int Kt, int Nmax, int nks, int SK, float* __restrict__ C, int ldc)
{
    __shared__ U32 sB[2][2][128][12];   // [buf][hi/lo][n][k2 padded to 12] = 48KB
    int tid = threadIdx.x;
    int lane = tid & 31, wid = tid >> 5;
    int warp_m = wid >> 1, warp_n = wid & 1;
    int n0 = blockIdx.x * 128;
    int z = blockIdx.y;
    int s0 = (int)((long long)z * nks / SK);
    int s1 = (int)((long long)(z + 1) * nks / SK);

    float acc[2][8][4];
#pragma unroll
    for (int i = 0; i < 2; i++)
#pragma unroll
        for (int j = 0; j < 8; j++)
#pragma unroll
            for (int q = 0; q < 4; q++) acc[i][j][q] = 0.0f;

    int brow = tid >> 1;                 // smem row this thread fills
    int bk4 = (tid & 1) * 4;             // u32 offset within row (0 or 4)
    // prologue: stage s0
    {
        const uint4* gh = (const uint4*)(Bh + (size_t)(n0 + brow) * Kt + s0 * 16) + (tid & 1);
        const uint4* gl = (const uint4*)(Bl + (size_t)(n0 + brow) * Kt + s0 * 16) + (tid & 1);
        *(uint4*)&sB[0][0][brow][bk4] = *gh;
        *(uint4*)&sB[0][1][brow][bk4] = *gl;
    }
    __syncthreads();

    int buf = 0;
    for (int ks = s0; ks < s1; ks++) {
        bool has = (ks + 1 < s1);
        uint4 nbh, nbl;
        if (has) {
            nbh = *((const uint4*)(Bh + (size_t)(n0 + brow) * Kt + (ks + 1) * 16) + (tid & 1));
            nbl = *((const uint4*)(Bl + (size_t)(n0 + brow) * Kt + (ks + 1) * 16) + (tid & 1));
        }
        // ---- A fragments (direct from global, L1/L2-cached) ----
        int k2b = ks * 8 + (lane & 3);
        U32 ah[2][4], al[2][4];
#pragma unroll
        for (int i = 0; i < 2; i++) {
            int r0 = warp_m * 32 + i * 16 + (lane >> 2);
            const U32* ph = AH2 + (size_t)k2b * BSZ + r0;
            const U32* pl = AL2 + (size_t)k2b * BSZ + r0;
            ah[i][0] = ph[0];       ah[i][1] = ph[8];
            ah[i][2] = ph[4 * BSZ]; ah[i][3] = ph[4 * BSZ + 8];
            al[i][0] = pl[0];       al[i][1] = pl[8];
            al[i][2] = pl[4 * BSZ]; al[i][3] = pl[4 * BSZ + 8];
        }
        // ---- B fragments from smem ----
        U32 bh[8][2], bl[8][2];
#pragma unroll
        for (int j = 0; j < 8; j++) {
            int nn = warp_n * 64 + j * 8 + (lane >> 2);
            bh[j][0] = sB[buf][0][nn][lane & 3];
            bh[j][1] = sB[buf][0][nn][(lane & 3) + 4];
            bl[j][0] = sB[buf][1][nn][lane & 3];
            bl[j][1] = sB[buf][1][nn][(lane & 3) + 4];
        }
        // ---- 48 MMAs in 3 term-passes (no RAW stalls) ----
#pragma unroll
        for (int j = 0; j < 8; j++) {
            mma16816(acc[0][j], ah[0], bh[j][0], bh[j][1]);
            mma16816(acc[1][j], ah[1], bh[j][0], bh[j][1]);
        }
#pragma unroll
        for (int j = 0; j < 8; j++) {
            mma16816(acc[0][j], al[0], bh[j][0], bh[j][1]);
            mma16816(acc[1][j], al[1], bh[j][0], bh[j][1]);
        }
#pragma unroll
        for (int j = 0; j < 8; j++) {
            mma16816(acc[0][j], ah[0], bl[j][0], bl[j][1]);
            mma16816(acc[1][j], ah[1], bl[j][0], bl[j][1]);
        }
        if (has) {
            *(uint4*)&sB[buf ^ 1][0][brow][bk4] = nbh;
            *(uint4*)&sB[buf ^ 1][1][brow][bk4] = nbl;
            __syncthreads();
            buf ^= 1;
        }
    }

    // ---- epilogue ----
    float* Cz = C + (size_t)z * BSZ * ldc;
#pragma unroll
    for (int i = 0; i < 2; i++) {
        int m0 = warp_m * 32 + i * 16 + (lane >> 2);
#pragma unroll
        for (int j = 0; j < 8; j++) {
            int n = n0 + warp_n * 64 + j * 8 + 2 * (lane & 3);
            if (n < Nmax) {
                Cz[(size_t)m0 * ldc + n]       = acc[i][j][0];
                Cz[(size_t)(m0 + 8) * ldc + n] = acc[i][j][2];
            }
            if (n + 1 < Nmax) {
                Cz[(size_t)m0 * ldc + n + 1]       = acc[i][j][1];
                Cz[(size_t)(m0 + 8) * ldc + n + 1] = acc[i][j][3];
            }
        }
    }
}

// ---------------- transpose + bf16 hi/lo split: dst[n][k] from src[k][ncols] ----------------
__global__ void k_transpose_split(const float* __restrict__ src, int K, int ncols,
                                  __nv_bfloat16* __restrict__ dh, __nv_bfloat16* __restrict__ dl)
{
    __shared__ float tile[32][33];
    int kb = blockIdx.x * 32, nb = blockIdx.y * 32;
    int tx = threadIdx.x, ty = threadIdx.y;   // 32 x 8
#pragma unroll
    for (int r = 0; r < 4; r++) {
        int k = kb + ty + 8 * r, n = nb + tx;
        tile[ty + 8 * r][tx] = (n < ncols) ? src[(size_t)k * ncols + n] : 0.0f;
    }
    __syncthreads();
#pragma unroll
    for (int r = 0; r < 4; r++) {
        int n = nb + ty + 8 * r, k = kb + tx;
        float v = tile[tx][ty + 8 * r];
        __nv_bfloat16 h = __float2bfloat16(v);
        __nv_bfloat16 l = __float2bfloat16(v - __bfloat162float(h));
        dh[(size_t)n * K + k] = h;
        dl[(size_t)n * K + k] = l;
    }
}

// ---------------- fused init (one launch) ----------------
__global__ void k_init_all(const float* __restrict__ x, const float* __restrict__ strc,
                           const float* __restrict__ sas, const float* __restrict__ w1,
                           const float* __restrict__ w2) {
    long long idx = blockIdx.x * 256LL + threadIdx.x;
    if (idx < R1) {       // xT [k][b]
        int i = (int)idx;
        g_xT[i] = x[(i & 127) * DIN + (i >> 7)];
        return;
    }
    idx -= R1;
    if (idx < R2) {       // trace [m][d][b]
        int i = (int)idx;
        int d = (i >> 7) & (DMODEL - 1);
        int m = i >> 18;
        g_trace[i] = strc[d * MEMN + m];
        return;
    }
    idx -= R2;
    if (idx < R3) {       // act [d][b] + H2/L2
        int i = (int)idx;
        int d = i >> 7, b = i & 127;
        float v = sas[d];
        g_actT[i] = v;
        hl_store(v, d, b, g_actH2, g_actL2);
        return;
    }
    idx -= R3;
    if (idx < R4) {       // w1 interleave
        int i = (int)idx;
        int d = i & (DMODEL - 1);
        int rem = i >> 11;
        int h = rem & 63, m = rem >> 6;
        g_w1i[((d * MEMN + m) * 32 + (h & 31)) * 2 + (h >> 5)] = w1[i];
        return;
    }
    idx -= R4;
    if (idx < R5) {       // w2 transpose
        int i = (int)idx;
        g_w2T[(i & (DMODEL - 1)) * 64 + (i >> 11)] = w2[i];
    }
}

__global__ void k_init_alpha(const float* __restrict__ sas, const float* __restrict__ decay,
                             const int* __restrict__ il, const int* __restrict__ ir) {
    int p = blockIdx.x, b = threadIdx.x;
    float pf = (float)p;
    int i = (int)floorf(256.5f - sqrtf(256.5f * 256.5f - 2.0f * pf));
    if (i < 0) i = 0;
    if (i > NSY - 1) i = NSY - 1;
    while (i > 0 && (i * NSY - i * (i - 1) / 2) > p) i--;
    while (i < NSY - 1 && ((i + 1) * NSY - (i + 1) * i / 2) <= p) i++;
    int j = i + (p - (i * NSY - i * (i - 1) / 2));
    if (b == 0) {
        g_pi[p] = i; g_pj[p] = j;
        g_r[p] = expf(-fminf(fmaxf(decay[p], 0.0f), 15.0f));
    }
    g_alpha[p * BSZ + b] = sas[il[i]] * sas[ir[j]];
}

// ---------------- FMA2 GEMM (one-time z0 = x @ W_top, exact fp32) ----------------
__global__ __launch_bounds__(256) void k_gemm_f2(
    const float* __restrict__ A, const float* __restrict__ B,
    int ldb, int nkb, float* __restrict__ C, int ldc)
{
    __shared__ float As[2][8][128];
    __shared__ float Bs[2][8][128];
    int n0 = blockIdx.x * 128;
    int tid = threadIdx.x;
    int lr = tid >> 5, lc = (tid & 31) * 4;
    int ty = tid >> 4, tx = tid & 15;
    ULL acc[8][4];
#pragma unroll
    for (int i = 0; i < 8; i++)
#pragma unroll
        for (int j = 0; j < 4; j++) acc[i][j] = 0ULL;
    float4 pa = *(const float4*)(A + lr * BSZ + lc);
    float4 pb = *(const float4*)(B + (size_t)lr * ldb + n0 + lc);
    *(float4*)&As[0][lr][lc] = pa;
    *(float4*)&Bs[0][lr][lc] = pb;
    __syncthreads();
    int buf = 0;
    for (int kb = 0; kb < nkb; kb++) {
        bool has = (kb + 1 < nkb);
        if (has) {
            int krow = (kb + 1) * 8 + lr;
            pa = *(const float4*)(A + krow * BSZ + lc);
            pb = *(const float4*)(B + (size_t)krow * ldb + n0 + lc);
        }
#pragma unroll
        for (int kk = 0; kk < 8; kk++) {
            float a[8];
            *(float4*)&a[0] = *(const float4*)&As[buf][kk][ty * 8];
            *(float4*)&a[4] = *(const float4*)&As[buf][kk][ty * 8 + 4];
            ULL bv[4];
            const ULL* bp = (const ULL*)&Bs[buf][kk][tx * 8];
#pragma unroll
            for (int j = 0; j < 4; j++) bv[j] = bp[j];
#pragma unroll
            for (int i = 0; i < 8; i++) {
                ULL ad = dup2(a[i]);
#pragma unroll
                for (int j = 0; j < 4; j++) fma2(acc[i][j], ad, bv[j]);
            }
        }
        if (has) {
            *(float4*)&As[buf ^ 1][lr][lc] = pa;
            *(float4*)&Bs[buf ^ 1][lr][lc] = pb;
            __syncthreads();
            buf ^= 1;
        }
    }
#pragma unroll
    for (int i = 0; i < 8; i++) {
        int m = ty * 8 + i;
#pragma unroll
        for (int j = 0; j < 4; j++) {
            int n = n0 + tx * 8 + 2 * j;
            C[(size_t)m * ldc + n]     = lo32(acc[i][j]);
            C[(size_t)m * ldc + n + 1] = hi32(acc[i][j]);
        }
    }
}

// ---------------- GLU + LayerNorm -> trace slot ----------------
__global__ __launch_bounds__(256) void k_glu_ln(const float* __restrict__ syn_b,
                                                const float* __restrict__ ln_g,
                                                const float* __restrict__ ln_b, int slot) {
    int b = blockIdx.x, tid = threadIdx.x;
    __shared__ float sv[DMODEL];
    __shared__ float red[256];
    float s1 = 0.f, s2 = 0.f;
    for (int d = tid; d < DMODEL; d += 256) {
        float za = syn_b[d] + g_z0[b * N1 + d];
        float zb = syn_b[d + DMODEL] + g_z0[b * N1 + DMODEL + d];
#pragma unroll
        for (int s = 0; s < SK1; s++) {
            za += g_zp[(s * BSZ + b) * N1 + d];
            zb += g_zp[(s * BSZ + b) * N1 + DMODEL + d];
        }
        float v = za * sigmoidf_(zb);
        sv[d] = v; s1 += v; s2 += v * v;
    }
    red[tid] = s1; __syncthreads();
    for (int s = 128; s > 0; s >>= 1) { if (tid < s) red[tid] += red[tid + s]; __syncthreads(); }
    float mu = red[0] / (float)DMODEL;
    __syncthreads();
    red[tid] = s2; __syncthreads();
    for (int s = 128; s > 0; s >>= 1) { if (tid < s) red[tid] += red[tid + s]; __syncthreads(); }
    float inv = rsqrtf(red[0] / (float)DMODEL - mu * mu + 1e-5f);
    for (int d = tid; d < DMODEL; d += 256)
        g_trace[(slot * DMODEL + d) * BSZ + b] = (sv[d] - mu) * inv * ln_g[d] + ln_b[d];
}

// ---------------- trace_proc ----------------
__global__ __launch_bounds__(128) void k_traceproc(const float* __restrict__ b1,
                                                   const float* __restrict__ b2, int t) {
    int d = blockIdx.x, b = threadIdx.x;
    __shared__ float ws[MEMN * 64];
    const float* src = g_w1i + d * (MEMN * 64);
    for (int i = b; i < MEMN * 64; i += 128) ws[i] = src[i];
    __syncthreads();
    ULL trp[MEMN];
    int base = (t + 1) % MEMN;
#pragma unroll
    for (int m = 0; m < MEMN; m++) {
        int pm = base + m; if (pm >= MEMN) pm -= MEMN;
        trp[m] = dup2(g_trace[(pm * DMODEL + d) * BSZ + b]);
    }
    const float* b1d = b1 + d * 64;
    const float* w2d = g_w2T + d * 64;
    float o0 = b2[d * 2], o1 = b2[d * 2 + 1];
#pragma unroll
    for (int h2 = 0; h2 < 32; h2 += 2) {
        ULL acc0 = pack2(b1d[h2],     b1d[h2 + 32]);
        ULL acc1 = pack2(b1d[h2 + 1], b1d[h2 + 33]);
        const ULL* wp = ((const ULL*)ws) + h2;
#pragma unroll
        for (int m = 0; m < MEMN; m++) {
            fma2(acc0, trp[m], wp[m * 32]);
            fma2(acc1, trp[m], wp[m * 32 + 1]);
        }
        float h0 = lo32(acc0) * sigmoidf_(hi32(acc0));
        float h1 = lo32(acc1) * sigmoidf_(hi32(acc1));
        o0 += h0 * w2d[h2 * 2]     + h1 * w2d[(h2 + 1) * 2];
        o1 += h0 * w2d[h2 * 2 + 1] + h1 * w2d[(h2 + 1) * 2 + 1];
    }
    float act = o0 * sigmoidf_(o1);
    g_actT[d * BSZ + b] = act;
    hl_store(act, d, b, g_actH2, g_actL2);
}

// ---------------- pairwise + alpha + sync ----------------
__global__ __launch_bounds__(256) void k_syncpair(const int* __restrict__ il,
                                                  const int* __restrict__ ir, int t) {
    int p = blockIdx.x * 2 + threadIdx.y;
    int b = threadIdx.x;
    float l  = g_actT[il[g_pi[p]] * BSZ + b];
    float rr = g_actT[ir[g_pj[p]] * BSZ + b];
    float r = g_r[p];
    float a = r * g_alpha[p * BSZ + b] + l * rr;
    g_alpha[p * BSZ + b] = a;
    float beta = 1.0f;
    for (int k = 0; k <= t; k++) beta = r * beta + 1.0f;
    float s = a / sqrtf(beta);
    hl_store(s, p, b, g_syncH2, g_syncL2);
}

// ---------------- reduce + bias + preds + entropy ----------------
__global__ __launch_bounds__(256) void k_finish(const float* __restrict__ outb,
                                                float* __restrict__ dout, int t) {
    int b = blockIdx.x, tid = threadIdx.x;
    __shared__ float sp[OUTD];
    __shared__ float red[256];
    for (int n = tid; n < OUTD; n += 256) {
        float v = outb[n];
#pragma unroll
        for (int s = 0; s < SK2; s++) v += g_part[(s * BSZ + b) * OUTD + n];
        sp[n] = v;
        dout[(b * OUTD + n) * NITER + t] = v;
    }
    __syncthreads();
    float mx = -3.4e38f;
    for (int n = tid; n < OUTD; n += 256) mx = fmaxf(mx, sp[n]);
    red[tid] = mx; __syncthreads();
    for (int s = 128; s > 0; s >>= 1) { if (tid < s) red[tid] = fmaxf(red[tid], red[tid + s]); __syncthreads(); }
    float smax = red[0];
    __syncthreads();
    float se = 0.f;
    for (int n = tid; n < OUTD; n += 256) se += expf(sp[n] - smax);
    red[tid] = se; __syncthreads();
    for (int s = 128; s > 0; s >>= 1) { if (tid < s) red[tid] += red[tid + s]; __syncthreads(); }
    float lse = smax + logf(red[0]);
    __syncthreads();
    float ent = 0.f;
    for (int n = tid; n < OUTD; n += 256) { float lp = sp[n] - lse; ent += expf(lp) * lp; }
    red[tid] = ent; __syncthreads();
    for (int s = 128; s > 0; s >>= 1) { if (tid < s) red[tid] += red[tid + s]; __syncthreads(); }
    if (tid == 0) {
        float ne = -red[0] / logf(1000.0f);
        dout[CERT_OFF + (b * 2 + 0) * NITER + t] = ne;
        dout[CERT_OFF + (b * 2 + 1) * NITER + t] = 1.0f - ne;
    }
}

// ---------------- host ----------------
extern "C" void kernel_launch(void* const* d_in, const int* in_sizes, int n_in,
                              void* d_out, int out_size) {
    const float* x      = (const float*)d_in[0];
    const float* syn_w  = (const float*)d_in[1];
    const float* syn_b  = (const float*)d_in[2];
    const float* ln_g   = (const float*)d_in[3];
    const float* ln_b   = (const float*)d_in[4];
    const float* tp_w1  = (const float*)d_in[5];
    const float* tp_b1  = (const float*)d_in[6];
    const float* tp_w2  = (const float*)d_in[7];
    const float* tp_b2  = (const float*)d_in[8];
    const float* sas    = (const float*)d_in[9];
    const float* strc   = (const float*)d_in[10];
    const float* decay  = (const float*)d_in[11];
    const float* out_w  = (const float*)d_in[12];
    const float* out_b  = (const float*)d_in[13];
    const int*   il     = (const int*)d_in[14];
    const int*   ir     = (const int*)d_in[15];
    float* out = (float*)d_out;

    float *p_xT, *p_z0, *p_zp, *p_part;
    U32 *p_actH2, *p_actL2, *p_syncH2, *p_syncL2;
    __nv_bfloat16 *p_synTh, *p_synTl, *p_outTh, *p_outTl;
    cudaGetSymbolAddress((void**)&p_xT,     g_xT);
    cudaGetSymbolAddress((void**)&p_z0,     g_z0);
    cudaGetSymbolAddress((void**)&p_zp,     g_zp);
    cudaGetSymbolAddress((void**)&p_part,   g_part);
    cudaGetSymbolAddress((void**)&p_actH2,  g_actH2);
    cudaGetSymbolAddress((void**)&p_actL2,  g_actL2);
    cudaGetSymbolAddress((void**)&p_syncH2, g_syncH2);
    cudaGetSymbolAddress((void**)&p_syncL2, g_syncL2);
    cudaGetSymbolAddress((void**)&p_synTh,  g_synTh);
    cudaGetSymbolAddress((void**)&p_synTl,  g_synTl);
    cudaGetSymbolAddress((void**)&p_outTh,  g_outTh);
    cudaGetSymbolAddress((void**)&p_outTl,  g_outTl);

    // exactly 5 setup launches -> ncu -s 5 profiles the first k_gemm_mma
    k_init_all<<<RTOT / 256, 256>>>(x, strc, sas, tp_w1, tp_w2);
    k_init_alpha<<<NSYNC, BSZ>>>(sas, decay, il, ir);
    k_gemm_f2<<<N1 / 128, 256>>>(p_xT, syn_w, N1, DIN / 8, p_z0, N1);
    k_transpose_split<<<dim3(DMODEL / 32, N1 / 32), dim3(32, 8)>>>(
        syn_w + (size_t)DIN * N1, DMODEL, N1, p_synTh, p_synTl);
    k_transpose_split<<<dim3(NSYNC / 32, OUTPAD / 32), dim3(32, 8)>>>(
        out_w, NSYNC, OUTD, p_outTh, p_outTl);

    for (int t = 0; t < NITER; t++) {
        k_gemm_mma<<<dim3(N1 / 128, SK1), 256>>>(p_actH2, p_actL2, p_synTh, p_synTl,
                                                 DMODEL, N1, DMODEL / 16, SK1, p_zp, N1);
        k_glu_ln<<<BSZ, 256>>>(syn_b, ln_g, ln_b, t % MEMN);
        k_traceproc<<<DMODEL, BSZ>>>(tp_b1, tp_b2, t);
        k_syncpair<<<NSYNC / 2, dim3(BSZ, 2)>>>(il, ir, t);
        k_gemm_mma<<<dim3(OUTPAD / 128, SK2), 256>>>(p_syncH2, p_syncL2, p_outTh, p_outTl,
                                                     NSYNC, OUTD, NSYNC / 16, SK2, p_part, OUTD);
        k_finish<<<BSZ, 256>>>(out_b, out, t);
    }
}

// round 7
// speedup vs baseline: 2.5659x; 1.1399x over previous
#include <cuda_runtime.h>
#include <cuda_bf16.h>
#include <math.h>

#define BSZ    128
#define DIN    512
#define DMODEL 2048
#define MEMN   25
#define NSY    256
#define NSYNC  32896
#define OUTD   1000
#define OUTPAD 1024
#define NITER  24
#define N1     4096
#define SK1    4
#define SK2    18
#define CERT_OFF (BSZ * OUTD * NITER)

// init ranges
#define R1 (DIN * BSZ)
#define R2 (MEMN * DMODEL * BSZ)
#define R3 (DMODEL * BSZ)
#define R4 (MEMN * 64 * DMODEL)
#define R5 (64 * DMODEL)
#define RTOT (R1 + R2 + R3 + R4 + R5)

typedef unsigned long long ULL;
typedef unsigned U32;

// ---------------- persistent scratch ----------------
__device__ float g_trace[MEMN * DMODEL * BSZ];
__device__ float g_actT [DMODEL * BSZ];            // fp32 [d][b] for pairwise gather
__device__ U32   g_actH2[DMODEL / 2 * BSZ];        // bf16-hi pairs: u32[k2][m]
__device__ U32   g_actL2[DMODEL / 2 * BSZ];        // bf16-lo pairs
__device__ U32   g_syncH2[NSYNC / 2 * BSZ];
__device__ U32   g_syncL2[NSYNC / 2 * BSZ];
__device__ float g_xT   [DIN * BSZ];
__device__ float g_z0   [BSZ * N1];
__device__ float g_zp   [SK1 * BSZ * N1];
__device__ float g_alpha[NSYNC * BSZ];
__device__ float g_r    [NSYNC];
__device__ int   g_pi   [NSYNC];
__device__ int   g_pj   [NSYNC];
__device__ float g_part [SK2 * BSZ * OUTD];
__device__ float g_w1i  [DMODEL * MEMN * 64];
__device__ float g_w2T  [DMODEL * 64];
__device__ __nv_bfloat16 g_synTh[(size_t)N1 * DMODEL];      // [n][k]
__device__ __nv_bfloat16 g_synTl[(size_t)N1 * DMODEL];
__device__ __nv_bfloat16 g_outTh[(size_t)OUTPAD * NSYNC];   // [n][k], rows >= OUTD zero
__device__ __nv_bfloat16 g_outTl[(size_t)OUTPAD * NSYNC];

__device__ __forceinline__ float sigmoidf_(float x) { return 1.0f / (1.0f + expf(-x)); }
__device__ __forceinline__ ULL dup2(float x) {
    ULL r; unsigned u = __float_as_uint(x);
    asm("mov.b64 %0, {%1, %1};" : "=l"(r) : "r"(u)); return r;
}
__device__ __forceinline__ ULL pack2(float lo, float hi) {
    ULL r; asm("mov.b64 %0, {%1, %2};" : "=l"(r) : "r"(__float_as_uint(lo)), "r"(__float_as_uint(hi)));
    return r;
}
__device__ __forceinline__ void fma2(ULL& d, ULL a, ULL b) {
    asm("fma.rn.f32x2 %0, %1, %2, %3;" : "=l"(d) : "l"(a), "l"(b), "l"(d));
}
__device__ __forceinline__ float lo32(ULL v) { return __uint_as_float((unsigned)v); }
__device__ __forceinline__ float hi32(ULL v) { return __uint_as_float((unsigned)(v >> 32)); }

__device__ __forceinline__ void hl_store(float v, int k, int m,
                                         U32* __restrict__ H2, U32* __restrict__ L2) {
    __nv_bfloat16 h = __float2bfloat16(v);
    __nv_bfloat16 l = __float2bfloat16(v - __bfloat162float(h));
    __nv_bfloat16* ph = (__nv_bfloat16*)H2;
    __nv_bfloat16* pl = (__nv_bfloat16*)L2;
    int idx = (k >> 1) * (2 * BSZ) + m * 2 + (k & 1);
    ph[idx] = h;
    pl[idx] = l;
}

__device__ __forceinline__ U32 smem_u32(const void* p) {
    U32 a; asm("{ .reg .u64 t; cvta.to.shared.u64 t, %1; cvt.u32.u64 %0, t; }" : "=r"(a) : "l"(p));
    return a;
}
__device__ __forceinline__ void cp_async16(U32 saddr, const void* g) {
    asm volatile("cp.async.cg.shared.global [%0], [%1], 16;" :: "r"(saddr), "l"(g));
}
__device__ __forceinline__ void cp_commit() { asm volatile("cp.async.commit_group;" ::: "memory"); }
__device__ __forceinline__ void cp_wait0()  { asm volatile("cp.async.wait_group 0;" ::: "memory"); }

__device__ __forceinline__ void mma16816(float* c, const U32* a, U32 b0, U32 b1) {
    asm volatile("mma.sync.aligned.m16n8k16.row.col.f32.bf16.bf16.f32 "
                 "{%0,%1,%2,%3}, {%4,%5,%6,%7}, {%8,%9}, {%0,%1,%2,%3};"
                 : "+f"(c[0]), "+f"(c[1]), "+f"(c[2]), "+f"(c[3])
                 : "r"(a[0]), "r"(a[1]), "r"(a[2]), "r"(a[3]), "r"(b0), "r"(b1));
}

// load A fragments (hi+lo) for k-step ks
__device__ __forceinline__ void load_afrag(const U32* __restrict__ AH2, const U32* __restrict__ AL2,
                                           int ks, int lane, int warp_m,
                                           U32 ah[2][4], U32 al[2][4]) {
    int k2b = ks * 8 + (lane & 3);
#pragma unroll
    for (int i = 0; i < 2; i++) {
        int r0 = warp_m * 32 + i * 16 + (lane >> 2);
        const U32* ph = AH2 + (size_t)k2b * BSZ + r0;
        const U32* pl = AL2 + (size_t)k2b * BSZ + r0;
        ah[i][0] = ph[0];       ah[i][1] = ph[8];
        ah[i][2] = ph[4 * BSZ]; ah[i][3] = ph[4 * BSZ + 8];
        al[i][0] = pl[0];       al[i][1] = pl[8];
        al[i][2] = pl[4 * BSZ]; al[i][3] = pl[4 * BSZ + 8];
    }
}

// B-frag LDS + 48 MMAs (3 term passes)
__device__ __forceinline__ void mma_step(float acc[2][8][4],
                                         const U32 ah[2][4], const U32 al[2][4],
                                         const U32* __restrict__ sBh, const U32* __restrict__ sBl,
                                         int warp_n, int lane) {
    U32 bh[8][2], bl[8][2];
#pragma unroll
    for (int j = 0; j < 8; j++) {
        int nn = warp_n * 64 + j * 8 + (lane >> 2);
        int c0 = nn * 12 + (lane & 3);
        bh[j][0] = sBh[c0];     bh[j][1] = sBh[c0 + 4];
        bl[j][0] = sBl[c0];     bl[j][1] = sBl[c0 + 4];
    }
#pragma unroll
    for (int j = 0; j < 8; j++) {
        mma16816(acc[0][j], ah[0], bh[j][0], bh[j][1]);
        mma16816(acc[1][j], ah[1], bh[j][0], bh[j][1]);
    }
#pragma unroll
    for (int j = 0; j < 8; j++) {
        mma16816(acc[0][j], al[0], bh[j][0], bh[j][1]);
        mma16816(acc[1][j], al[1], bh[j][0], bh[j][1]);
    }
#pragma unroll
    for (int j = 0; j < 8; j++) {
        mma16816(acc[0][j], ah[0], bl[j][0], bl[j][1]);
        mma16816(acc[1][j], ah[1], bl[j][0], bl[j][1]);
    }
}

// ================= HMMA GEMM (A-reg double buffer + cp.async B) =================
__global__ __launch_bounds__(256) void k_gemm_mma(
    const U32* __restrict__ AH2, const U32* __restrict__ AL2,
    const __nv_bfloat16* __restrict__ Bh, const __nv_bfloat16* __restrict__ Bl,
    int Kt, int Nmax, int nks, int SK, float* __restrict__ C, int ldc)
{
    __shared__ U32 sB[2][2][128][12];   // [buf][hi/lo][n][k2 pad 12] = 48KB
    int tid = threadIdx.x;
    int lane = tid & 31, wid = tid >> 5;
    int warp_m = wid >> 1, warp_n = wid & 1;
    int n0 = blockIdx.x * 128;
    int z = blockIdx.y;
    int s0 = (int)((long long)z * nks / SK);
    int s1 = (int)((long long)(z + 1) * nks / SK);

    float acc[2][8][4];
#pragma unroll
    for (int i = 0; i < 2; i++)
#pragma unroll
        for (int j = 0; j < 8; j++)
#pragma unroll
            for (int q = 0; q < 4; q++) acc[i][j][q] = 0.0f;

    int brow = tid >> 1;
    U32 sdst_h0 = smem_u32(&sB[0][0][brow][(tid & 1) * 4]);
    U32 sdst_l0 = smem_u32(&sB[0][1][brow][(tid & 1) * 4]);
    U32 sdst_h1 = smem_u32(&sB[1][0][brow][(tid & 1) * 4]);
    U32 sdst_l1 = smem_u32(&sB[1][1][brow][(tid & 1) * 4]);
    const __nv_bfloat16* gsrc_h = Bh + (size_t)(n0 + brow) * Kt + (tid & 1) * 8;
    const __nv_bfloat16* gsrc_l = Bl + (size_t)(n0 + brow) * Kt + (tid & 1) * 8;

    // prologue: stage B(s0), load A(s0)
    cp_async16(sdst_h0, gsrc_h + (size_t)s0 * 16);
    cp_async16(sdst_l0, gsrc_l + (size_t)s0 * 16);
    cp_commit();
    U32 a0h[2][4], a0l[2][4], a1h[2][4], a1l[2][4];
    load_afrag(AH2, AL2, s0, lane, warp_m, a0h, a0l);
    cp_wait0();
    __syncthreads();

    int buf = 0;
    int ks = s0;
    while (ks < s1) {
        // ---- step with a0 ----
        {
            bool has = (ks + 1 < s1);
            if (has) {
                U32 dh = buf ? sdst_h0 : sdst_h1;
                U32 dl = buf ? sdst_l0 : sdst_l1;
                cp_async16(dh, gsrc_h + (size_t)(ks + 1) * 16);
                cp_async16(dl, gsrc_l + (size_t)(ks + 1) * 16);
                cp_commit();
                load_afrag(AH2, AL2, ks + 1, lane, warp_m, a1h, a1l);
            }
            mma_step(acc, a0h, a0l, &sB[buf][0][0][0], &sB[buf][1][0][0], warp_n, lane);
            if (has) { cp_wait0(); __syncthreads(); buf ^= 1; }
        }
        ks++;
        if (ks >= s1) break;
        // ---- step with a1 ----
        {
            bool has = (ks + 1 < s1);
            if (has) {
                U32 dh = buf ? sdst_h0 : sdst_h1;
                U32 dl = buf ? sdst_l0 : sdst_l1;
                cp_async16(dh, gsrc_h + (size_t)(ks + 1) * 16);
                cp_async16(dl, gsrc_l + (size_t)(ks + 1) * 16);
                cp_commit();
                load_afrag(AH2, AL2, ks + 1, lane, warp_m, a0h, a0l);
            }
            mma_step(acc, a1h, a1l, &sB[buf][0][0][0], &sB[buf][1][0][0], warp_n, lane);
            if (has) { cp_wait0(); __syncthreads(); buf ^= 1; }
        }
        ks++;
    }

    float* Cz = C + (size_t)z * BSZ * ldc;
#pragma unroll
    for (int i = 0; i < 2; i++) {
        int m0 = warp_m * 32 + i * 16 + (lane >> 2);
#pragma unroll
        for (int j = 0; j < 8; j++) {
            int n = n0 + warp_n * 64 + j * 8 + 2 * (lane & 3);
            if (n < Nmax) {
                Cz[(size_t)m0 * ldc + n]       = acc[i][j][0];
                Cz[(size_t)(m0 + 8) * ldc + n] = acc[i][j][2];
            }
            if (n + 1 < Nmax) {
                Cz[(size_t)m0 * ldc + n + 1]       = acc[i][j][1];
                Cz[(size_t)(m0 + 8) * ldc + n + 1] = acc[i][j][3];
            }
        }
    }
}

// ---------------- transpose + bf16 hi/lo split ----------------
__global__ void k_transpose_split(const float* __restrict__ src, int K, int ncols,
                                  __nv_bfloat16* __restrict__ dh, __nv_bfloat16* __restrict__ dl)
{
    __shared__ float tile[32][33];
    int kb = blockIdx.x * 32, nb = blockIdx.y * 32;
    int tx = threadIdx.x, ty = threadIdx.y;
#pragma unroll
    for (int r = 0; r < 4; r++) {
        int k = kb + ty + 8 * r, n = nb + tx;
        tile[ty + 8 * r][tx] = (n < ncols) ? src[(size_t)k * ncols + n] : 0.0f;
    }
    __syncthreads();
#pragma unroll
    for (int r = 0; r < 4; r++) {
        int n = nb + ty + 8 * r, k = kb + tx;
        float v = tile[tx][ty + 8 * r];
        __nv_bfloat16 h = __float2bfloat16(v);
        __nv_bfloat16 l = __float2bfloat16(v - __bfloat162float(h));
        dh[(size_t)n * K + k] = h;
        dl[(size_t)n * K + k] = l;
    }
}

// ---------------- fused init ----------------
__global__ void k_init_all(const float* __restrict__ x, const float* __restrict__ strc,
                           const float* __restrict__ sas, const float* __restrict__ w1,
                           const float* __restrict__ w2) {
    long long idx = blockIdx.x * 256LL + threadIdx.x;
    if (idx < R1) {
        int i = (int)idx;
        g_xT[i] = x[(i & 127) * DIN + (i >> 7)];
        return;
    }
    idx -= R1;
    if (idx < R2) {
        int i = (int)idx;
        int d = (i >> 7) & (DMODEL - 1);
        int m = i >> 18;
        g_trace[i] = strc[d * MEMN + m];
        return;
    }
    idx -= R2;
    if (idx < R3) {
        int i = (int)idx;
        int d = i >> 7, b = i & 127;
        float v = sas[d];
        g_actT[i] = v;
        hl_store(v, d, b, g_actH2, g_actL2);
        return;
    }
    idx -= R3;
    if (idx < R4) {
        int i = (int)idx;
        int d = i & (DMODEL - 1);
        int rem = i >> 11;
        int h = rem & 63, m = rem >> 6;
        g_w1i[((d * MEMN + m) * 32 + (h & 31)) * 2 + (h >> 5)] = w1[i];
        return;
    }
    idx -= R4;
    if (idx < R5) {
        int i = (int)idx;
        g_w2T[(i & (DMODEL - 1)) * 64 + (i >> 11)] = w2[i];
    }
}

__global__ void k_init_alpha(const float* __restrict__ sas, const float* __restrict__ decay,
                             const int* __restrict__ il, const int* __restrict__ ir) {
    int p = blockIdx.x, b = threadIdx.x;
    float pf = (float)p;
    int i = (int)floorf(256.5f - sqrtf(256.5f * 256.5f - 2.0f * pf));
    if (i < 0) i = 0;
    if (i > NSY - 1) i = NSY - 1;
    while (i > 0 && (i * NSY - i * (i - 1) / 2) > p) i--;
    while (i < NSY - 1 && ((i + 1) * NSY - (i + 1) * i / 2) <= p) i++;
    int j = i + (p - (i * NSY - i * (i - 1) / 2));
    if (b == 0) {
        g_pi[p] = i; g_pj[p] = j;
        g_r[p] = expf(-fminf(fmaxf(decay[p], 0.0f), 15.0f));
    }
    g_alpha[p * BSZ + b] = sas[il[i]] * sas[ir[j]];
}

// ---------------- FMA2 GEMM (one-time z0 = x @ W_top, exact fp32) ----------------
__global__ __launch_bounds__(256) void k_gemm_f2(
    const float* __restrict__ A, const float* __restrict__ B,
    int ldb, int nkb, float* __restrict__ C, int ldc)
{
    __shared__ float As[2][8][128];
    __shared__ float Bs[2][8][128];
    int n0 = blockIdx.x * 128;
    int tid = threadIdx.x;
    int lr = tid >> 5, lc = (tid & 31) * 4;
    int ty = tid >> 4, tx = tid & 15;
    ULL acc[8][4];
#pragma unroll
    for (int i = 0; i < 8; i++)
#pragma unroll
        for (int j = 0; j < 4; j++) acc[i][j] = 0ULL;
    float4 pa = *(const float4*)(A + lr * BSZ + lc);
    float4 pb = *(const float4*)(B + (size_t)lr * ldb + n0 + lc);
    *(float4*)&As[0][lr][lc] = pa;
    *(float4*)&Bs[0][lr][lc] = pb;
    __syncthreads();
    int buf = 0;
    for (int kb = 0; kb < nkb; kb++) {
        bool has = (kb + 1 < nkb);
        if (has) {
            int krow = (kb + 1) * 8 + lr;
            pa = *(const float4*)(A + krow * BSZ + lc);
            pb = *(const float4*)(B + (size_t)krow * ldb + n0 + lc);
        }
#pragma unroll
        for (int kk = 0; kk < 8; kk++) {
            float a[8];
            *(float4*)&a[0] = *(const float4*)&As[buf][kk][ty * 8];
            *(float4*)&a[4] = *(const float4*)&As[buf][kk][ty * 8 + 4];
            ULL bv[4];
            const ULL* bp = (const ULL*)&Bs[buf][kk][tx * 8];
#pragma unroll
            for (int j = 0; j < 4; j++) bv[j] = bp[j];
#pragma unroll
            for (int i = 0; i < 8; i++) {
                ULL ad = dup2(a[i]);
#pragma unroll
                for (int j = 0; j < 4; j++) fma2(acc[i][j], ad, bv[j]);
            }
        }
        if (has) {
            *(float4*)&As[buf ^ 1][lr][lc] = pa;
            *(float4*)&Bs[buf ^ 1][lr][lc] = pb;
            __syncthreads();
            buf ^= 1;
        }
    }
#pragma unroll
    for (int i = 0; i < 8; i++) {
        int m = ty * 8 + i;
#pragma unroll
        for (int j = 0; j < 4; j++) {
            int n = n0 + tx * 8 + 2 * j;
            C[(size_t)m * ldc + n]     = lo32(acc[i][j]);
            C[(size_t)m * ldc + n + 1] = hi32(acc[i][j]);
        }
    }
}

// ---------------- GLU + LayerNorm -> trace slot ----------------
__global__ __launch_bounds__(256) void k_glu_ln(const float* __restrict__ syn_b,
                                                const float* __restrict__ ln_g,
                                                const float* __restrict__ ln_b, int slot) {
    int b = blockIdx.x, tid = threadIdx.x;
    __shared__ float sv[DMODEL];
    __shared__ float red[256];
    float s1 = 0.f, s2 = 0.f;
    for (int d = tid; d < DMODEL; d += 256) {
        float za = syn_b[d] + g_z0[b * N1 + d];
        float zb = syn_b[d + DMODEL] + g_z0[b * N1 + DMODEL + d];
#pragma unroll
        for (int s = 0; s < SK1; s++) {
            za += g_zp[(s * BSZ + b) * N1 + d];
            zb += g_zp[(s * BSZ + b) * N1 + DMODEL + d];
        }
        float v = za * sigmoidf_(zb);
        sv[d] = v; s1 += v; s2 += v * v;
    }
    red[tid] = s1; __syncthreads();
    for (int s = 128; s > 0; s >>= 1) { if (tid < s) red[tid] += red[tid + s]; __syncthreads(); }
    float mu = red[0] / (float)DMODEL;
    __syncthreads();
    red[tid] = s2; __syncthreads();
    for (int s = 128; s > 0; s >>= 1) { if (tid < s) red[tid] += red[tid + s]; __syncthreads(); }
    float inv = rsqrtf(red[0] / (float)DMODEL - mu * mu + 1e-5f);
    for (int d = tid; d < DMODEL; d += 256)
        g_trace[(slot * DMODEL + d) * BSZ + b] = (sv[d] - mu) * inv * ln_g[d] + ln_b[d];
}

// ---------------- trace_proc ----------------
__global__ __launch_bounds__(128) void k_traceproc(const float* __restrict__ b1,
                                                   const float* __restrict__ b2, int t) {
    int d = blockIdx.x, b = threadIdx.x;
    __shared__ float ws[MEMN * 64];
    const float* src = g_w1i + d * (MEMN * 64);
    for (int i = b; i < MEMN * 64; i += 128) ws[i] = src[i];
    __syncthreads();
    ULL trp[MEMN];
    int base = (t + 1) % MEMN;
#pragma unroll
    for (int m = 0; m < MEMN; m++) {
        int pm = base + m; if (pm >= MEMN) pm -= MEMN;
        trp[m] = dup2(g_trace[(pm * DMODEL + d) * BSZ + b]);
    }
    const float* b1d = b1 + d * 64;
    const float* w2d = g_w2T + d * 64;
    float o0 = b2[d * 2], o1 = b2[d * 2 + 1];
#pragma unroll
    for (int h2 = 0; h2 < 32; h2 += 2) {
        ULL acc0 = pack2(b1d[h2],     b1d[h2 + 32]);
        ULL acc1 = pack2(b1d[h2 + 1], b1d[h2 + 33]);
        const ULL* wp = ((const ULL*)ws) + h2;
#pragma unroll
        for (int m = 0; m < MEMN; m++) {
            fma2(acc0, trp[m], wp[m * 32]);
            fma2(acc1, trp[m], wp[m * 32 + 1]);
        }
        float h0 = lo32(acc0) * sigmoidf_(hi32(acc0));
        float h1 = lo32(acc1) * sigmoidf_(hi32(acc1));
        o0 += h0 * w2d[h2 * 2]     + h1 * w2d[(h2 + 1) * 2];
        o1 += h0 * w2d[h2 * 2 + 1] + h1 * w2d[(h2 + 1) * 2 + 1];
    }
    float act = o0 * sigmoidf_(o1);
    g_actT[d * BSZ + b] = act;
    hl_store(act, d, b, g_actH2, g_actL2);
}

// ---------------- pairwise + alpha + sync ----------------
__global__ __launch_bounds__(256) void k_syncpair(const int* __restrict__ il,
                                                  const int* __restrict__ ir, int t) {
    int p = blockIdx.x * 2 + threadIdx.y;
    int b = threadIdx.x;
    float l  = g_actT[il[g_pi[p]] * BSZ + b];
    float rr = g_actT[ir[g_pj[p]] * BSZ + b];
    float r = g_r[p];
    float a = r * g_alpha[p * BSZ + b] + l * rr;
    g_alpha[p * BSZ + b] = a;
    float beta = 1.0f;
    for (int k = 0; k <= t; k++) beta = r * beta + 1.0f;
    float s = a / sqrtf(beta);
    hl_store(s, p, b, g_syncH2, g_syncL2);
}

// ---------------- reduce + bias + preds + entropy ----------------
__global__ __launch_bounds__(256) void k_finish(const float* __restrict__ outb,
                                                float* __restrict__ dout, int t) {
    int b = blockIdx.x, tid = threadIdx.x;
    __shared__ float sp[OUTD];
    __shared__ float red[256];
    for (int n = tid; n < OUTD; n += 256) {
        float v = outb[n];
#pragma unroll
        for (int s = 0; s < SK2; s++) v += g_part[(s * BSZ + b) * OUTD + n];
        sp[n] = v;
        dout[(b * OUTD + n) * NITER + t] = v;
    }
    __syncthreads();
    float mx = -3.4e38f;
    for (int n = tid; n < OUTD; n += 256) mx = fmaxf(mx, sp[n]);
    red[tid] = mx; __syncthreads();
    for (int s = 128; s > 0; s >>= 1) { if (tid < s) red[tid] = fmaxf(red[tid], red[tid + s]); __syncthreads(); }
    float smax = red[0];
    __syncthreads();
    float se = 0.f;
    for (int n = tid; n < OUTD; n += 256) se += expf(sp[n] - smax);
    red[tid] = se; __syncthreads();
    for (int s = 128; s > 0; s >>= 1) { if (tid < s) red[tid] += red[tid + s]; __syncthreads(); }
    float lse = smax + logf(red[0]);
    __syncthreads();
    float ent = 0.f;
    for (int n = tid; n < OUTD; n += 256) { float lp = sp[n] - lse; ent += expf(lp) * lp; }
    red[tid] = ent; __syncthreads();
    for (int s = 128; s > 0; s >>= 1) { if (tid < s) red[tid] += red[tid + s]; __syncthreads(); }
    if (tid == 0) {
        float ne = -red[0] / logf(1000.0f);
        dout[CERT_OFF + (b * 2 + 0) * NITER + t] = ne;
        dout[CERT_OFF + (b * 2 + 1) * NITER + t] = 1.0f - ne;
    }
}

// ---------------- host ----------------
extern "C" void kernel_launch(void* const* d_in, const int* in_sizes, int n_in,
                              void* d_out, int out_size) {
    const float* x      = (const float*)d_in[0];
    const float* syn_w  = (const float*)d_in[1];
    const float* syn_b  = (const float*)d_in[2];
    const float* ln_g   = (const float*)d_in[3];
    const float* ln_b   = (const float*)d_in[4];
    const float* tp_w1  = (const float*)d_in[5];
    const float* tp_b1  = (const float*)d_in[6];
    const float* tp_w2  = (const float*)d_in[7];
    const float* tp_b2  = (const float*)d_in[8];
    const float* sas    = (const float*)d_in[9];
    const float* strc   = (const float*)d_in[10];
    const float* decay  = (const float*)d_in[11];
    const float* out_w  = (const float*)d_in[12];
    const float* out_b  = (const float*)d_in[13];
    const int*   il     = (const int*)d_in[14];
    const int*   ir     = (const int*)d_in[15];
    float* out = (float*)d_out;

    float *p_xT, *p_z0, *p_zp, *p_part;
    U32 *p_actH2, *p_actL2, *p_syncH2, *p_syncL2;
    __nv_bfloat16 *p_synTh, *p_synTl, *p_outTh, *p_outTl;
    cudaGetSymbolAddress((void**)&p_xT,     g_xT);
    cudaGetSymbolAddress((void**)&p_z0,     g_z0);
    cudaGetSymbolAddress((void**)&p_zp,     g_zp);
    cudaGetSymbolAddress((void**)&p_part,   g_part);
    cudaGetSymbolAddress((void**)&p_actH2,  g_actH2);
    cudaGetSymbolAddress((void**)&p_actL2,  g_actL2);
    cudaGetSymbolAddress((void**)&p_syncH2, g_syncH2);
    cudaGetSymbolAddress((void**)&p_syncL2, g_syncL2);
    cudaGetSymbolAddress((void**)&p_synTh,  g_synTh);
    cudaGetSymbolAddress((void**)&p_synTl,  g_synTl);
    cudaGetSymbolAddress((void**)&p_outTh,  g_outTh);
    cudaGetSymbolAddress((void**)&p_outTl,  g_outTl);

    // launch order: the 4th launch is the first k_gemm_mma (for ncu targeting)
    k_init_all<<<RTOT / 256, 256>>>(x, strc, sas, tp_w1, tp_w2);
    k_transpose_split<<<dim3(DMODEL / 32, N1 / 32), dim3(32, 8)>>>(
        syn_w + (size_t)DIN * N1, DMODEL, N1, p_synTh, p_synTl);
    k_transpose_split<<<dim3(NSYNC / 32, OUTPAD / 32), dim3(32, 8)>>>(
        out_w, NSYNC, OUTD, p_outTh, p_outTl);

    for (int t = 0; t < NITER; t++) {
        k_gemm_mma<<<dim3(N1 / 128, SK1), 256>>>(p_actH2, p_actL2, p_synTh, p_synTl,
                                                 DMODEL, N1, DMODEL / 16, SK1, p_zp, N1);
        if (t == 0) {
            // needed before glu_ln / syncpair; stream order guarantees it
            k_gemm_f2<<<N1 / 128, 256>>>(p_xT, syn_w, N1, DIN / 8, p_z0, N1);
            k_init_alpha<<<NSYNC, BSZ>>>(sas, decay, il, ir);
        }
        k_glu_ln<<<BSZ, 256>>>(syn_b, ln_g, ln_b, t % MEMN);
        k_traceproc<<<DMODEL, BSZ>>>(tp_b1, tp_b2, t);
        k_syncpair<<<NSYNC / 2, dim3(BSZ, 2)>>>(il, ir, t);
        k_gemm_mma<<<dim3(OUTPAD / 128, SK2), 256>>>(p_syncH2, p_syncL2, p_outTh, p_outTl,
                                                     NSYNC, OUTD, NSYNC / 16, SK2, p_part, OUTD);
        k_finish<<<BSZ, 256>>>(out_b, out, t);
    }
}

// round 8
// speedup vs baseline: 3.0440x; 1.1863x over previous
#include <cuda_runtime.h>
#include <cuda_bf16.h>
#include <math.h>

#define BSZ    128
#define DIN    512
#define DMODEL 2048
#define MEMN   25
#define NSY    256
#define NSYNC  32896
#define OUTD   1000
#define OUTPAD 1024
#define NITER  24
#define N1     4096
#define SK1    8
#define SK2    36
#define CERT_OFF (BSZ * OUTD * NITER)

// init ranges
#define R1 (DIN * BSZ)
#define R2 (MEMN * DMODEL * BSZ)
#define R3 (DMODEL * BSZ)
#define R4 (MEMN * 64 * DMODEL)
#define R5 (64 * DMODEL)
#define RTOT (R1 + R2 + R3 + R4 + R5)

typedef unsigned long long ULL;
typedef unsigned U32;

// ---------------- persistent scratch ----------------
__device__ float g_trace[MEMN * DMODEL * BSZ];
__device__ float g_actT [DMODEL * BSZ];            // fp32 [d][b] for pairwise gather
__device__ U32   g_actH2[DMODEL / 2 * BSZ];        // bf16-hi, MMA-fragment-native layout
__device__ U32   g_actL2[DMODEL / 2 * BSZ];        // bf16-lo
__device__ U32   g_syncH2[NSYNC / 2 * BSZ];
__device__ U32   g_syncL2[NSYNC / 2 * BSZ];
__device__ float g_xT   [DIN * BSZ];
__device__ float g_z0   [BSZ * N1];
__device__ float g_zp   [SK1 * BSZ * N1];
__device__ float g_alpha[NSYNC * BSZ];
__device__ float g_r    [NSYNC];
__device__ int   g_pi   [NSYNC];
__device__ int   g_pj   [NSYNC];
__device__ float g_part [SK2 * BSZ * OUTD];
__device__ float g_w1i  [DMODEL * MEMN * 64];
__device__ float g_w2T  [DMODEL * 64];
__device__ __nv_bfloat16 g_synTh[(size_t)N1 * DMODEL];      // [n][k]
__device__ __nv_bfloat16 g_synTl[(size_t)N1 * DMODEL];
__device__ __nv_bfloat16 g_outTh[(size_t)OUTPAD * NSYNC];   // [n][k], rows >= OUTD zero
__device__ __nv_bfloat16 g_outTl[(size_t)OUTPAD * NSYNC];

__device__ __forceinline__ float sigmoidf_(float x) { return 1.0f / (1.0f + expf(-x)); }
__device__ __forceinline__ ULL dup2(float x) {
    ULL r; unsigned u = __float_as_uint(x);
    asm("mov.b64 %0, {%1, %1};" : "=l"(r) : "r"(u)); return r;
}
__device__ __forceinline__ ULL pack2(float lo, float hi) {
    ULL r; asm("mov.b64 %0, {%1, %2};" : "=l"(r) : "r"(__float_as_uint(lo)), "r"(__float_as_uint(hi)));
    return r;
}
__device__ __forceinline__ void fma2(ULL& d, ULL a, ULL b) {
    asm("fma.rn.f32x2 %0, %1, %2, %3;" : "=l"(d) : "l"(a), "l"(b), "l"(d));
}
__device__ __forceinline__ float lo32(ULL v) { return __uint_as_float((unsigned)v); }
__device__ __forceinline__ float hi32(ULL v) { return __uint_as_float((unsigned)(v >> 32)); }

// Fragment-native layout: u32 element (k2 = k>>1, m) lives so that each lane's
// 4-reg A-fragment is 16B contiguous and warps read 512B blocks.
// idx_u32 = ((ks*4 + mb)*2 + i)*128 + (rr*4+q)*4 + (h*2+rh)
//   ks=k2>>3, q=k2&3, h=(k2>>2)&1 ; mb=m>>5, i=(m>>4)&1, rh=(m>>3)&1, rr=m&7
__device__ __forceinline__ void hl_store(float v, int k, int m,
                                         U32* __restrict__ H2, U32* __restrict__ L2) {
    __nv_bfloat16 h = __float2bfloat16(v);
    __nv_bfloat16 l = __float2bfloat16(v - __bfloat162float(h));
    int k2 = k >> 1;
    int ks = k2 >> 3, q = k2 & 3, hh = (k2 >> 2) & 1;
    int mb = m >> 5, i = (m >> 4) & 1, rh = (m >> 3) & 1, rr = m & 7;
    int idx = ((((ks * 4 + mb) * 2 + i) * 128 + (rr * 4 + q) * 4 + (hh * 2 + rh)) << 1) + (k & 1);
    ((__nv_bfloat16*)H2)[idx] = h;
    ((__nv_bfloat16*)L2)[idx] = l;
}

__device__ __forceinline__ U32 smem_u32(const void* p) {
    U32 a; asm("{ .reg .u64 t; cvta.to.shared.u64 t, %1; cvt.u32.u64 %0, t; }" : "=r"(a) : "l"(p));
    return a;
}
__device__ __forceinline__ void cp_async16(U32 saddr, const void* g) {
    asm volatile("cp.async.cg.shared.global [%0], [%1], 16;" :: "r"(saddr), "l"(g));
}
__device__ __forceinline__ void cp_commit() { asm volatile("cp.async.commit_group;" ::: "memory"); }
__device__ __forceinline__ void cp_wait0()  { asm volatile("cp.async.wait_group 0;" ::: "memory"); }

__device__ __forceinline__ void mma16816(float* c, const U32* a, U32 b0, U32 b1) {
    asm volatile("mma.sync.aligned.m16n8k16.row.col.f32.bf16.bf16.f32 "
                 "{%0,%1,%2,%3}, {%4,%5,%6,%7}, {%8,%9}, {%0,%1,%2,%3};"
                 : "+f"(c[0]), "+f"(c[1]), "+f"(c[2]), "+f"(c[3])
                 : "r"(a[0]), "r"(a[1]), "r"(a[2]), "r"(a[3]), "r"(b0), "r"(b1));
}

// vectorized A-fragment load: 4x LDG.128, fully coalesced
__device__ __forceinline__ void load_afrag(const U32* __restrict__ AH2, const U32* __restrict__ AL2,
                                           int ks, int lane, int warp_m,
                                           uint4 ah[2], uint4 al[2]) {
    int base = ((ks * 4 + warp_m) * 2) * 128 + lane * 4;
    ah[0] = *(const uint4*)(AH2 + base);
    ah[1] = *(const uint4*)(AH2 + base + 128);
    al[0] = *(const uint4*)(AL2 + base);
    al[1] = *(const uint4*)(AL2 + base + 128);
}

// B-frag LDS + 48 MMAs in 3 term passes (bl loaded late to shorten lifetime)
__device__ __forceinline__ void mma_step(float acc[2][8][4],
                                         const uint4 ah[2], const uint4 al[2],
                                         const U32* __restrict__ sBh, const U32* __restrict__ sBl,
                                         int warp_n, int lane) {
    U32 bh[8][2];
#pragma unroll
    for (int j = 0; j < 8; j++) {
        int c0 = (warp_n * 64 + j * 8 + (lane >> 2)) * 12 + (lane & 3);
        bh[j][0] = sBh[c0];     bh[j][1] = sBh[c0 + 4];
    }
#pragma unroll
    for (int j = 0; j < 8; j++) {
        mma16816(acc[0][j], (const U32*)&ah[0], bh[j][0], bh[j][1]);
        mma16816(acc[1][j], (const U32*)&ah[1], bh[j][0], bh[j][1]);
    }
#pragma unroll
    for (int j = 0; j < 8; j++) {
        mma16816(acc[0][j], (const U32*)&al[0], bh[j][0], bh[j][1]);
        mma16816(acc[1][j], (const U32*)&al[1], bh[j][0], bh[j][1]);
    }
    U32 bl[8][2];
#pragma unroll
    for (int j = 0; j < 8; j++) {
        int c0 = (warp_n * 64 + j * 8 + (lane >> 2)) * 12 + (lane & 3);
        bl[j][0] = sBl[c0];     bl[j][1] = sBl[c0 + 4];
    }
#pragma unroll
    for (int j = 0; j < 8; j++) {
        mma16816(acc[0][j], (const U32*)&ah[0], bl[j][0], bl[j][1]);
        mma16816(acc[1][j], (const U32*)&ah[1], bl[j][0], bl[j][1]);
    }
}

// ================= HMMA GEMM (2 CTAs/SM, A-reg double buffer + cp.async B) =================
__global__ __launch_bounds__(256, 2) void k_gemm_mma(
    const U32* __restrict__ AH2, const U32* __restrict__ AL2,
    const __nv_bfloat16* __restrict__ Bh, const __nv_bfloat16* __restrict__ Bl,
    int Kt, int Nmax, int nks, int SK, float* __restrict__ C, int ldc)
{
    __shared__ U32 sB[2][2][128][12];   // [buf][hi/lo][n][k2 pad 12] = 48KB
    int tid = threadIdx.x;
    int lane = tid & 31, wid = tid >> 5;
    int warp_m = wid >> 1, warp_n = wid & 1;
    int n0 = blockIdx.x * 128;
    int z = blockIdx.y;
    int s0 = (int)((long long)z * nks / SK);
    int s1 = (int)((long long)(z + 1) * nks / SK);

    float acc[2][8][4];
#pragma unroll
    for (int i = 0; i < 2; i++)
#pragma unroll
        for (int j = 0; j < 8; j++)
#pragma unroll
            for (int q = 0; q < 4; q++) acc[i][j][q] = 0.0f;

    int brow = tid >> 1;
    U32 sdst_h0 = smem_u32(&sB[0][0][brow][(tid & 1) * 4]);
    U32 sdst_l0 = smem_u32(&sB[0][1][brow][(tid & 1) * 4]);
    U32 sdst_h1 = smem_u32(&sB[1][0][brow][(tid & 1) * 4]);
    U32 sdst_l1 = smem_u32(&sB[1][1][brow][(tid & 1) * 4]);
    const __nv_bfloat16* gsrc_h = Bh + (size_t)(n0 + brow) * Kt + (tid & 1) * 8;
    const __nv_bfloat16* gsrc_l = Bl + (size_t)(n0 + brow) * Kt + (tid & 1) * 8;

    // prologue: stage B(s0), load A(s0)
    cp_async16(sdst_h0, gsrc_h + (size_t)s0 * 16);
    cp_async16(sdst_l0, gsrc_l + (size_t)s0 * 16);
    cp_commit();
    uint4 a0h[2], a0l[2], a1h[2], a1l[2];
    load_afrag(AH2, AL2, s0, lane, warp_m, a0h, a0l);
    cp_wait0();
    __syncthreads();

    int buf = 0;
    int ks = s0;
    while (ks < s1) {
        {
            bool has = (ks + 1 < s1);
            if (has) {
                U32 dh = buf ? sdst_h0 : sdst_h1;
                U32 dl = buf ? sdst_l0 : sdst_l1;
                cp_async16(dh, gsrc_h + (size_t)(ks + 1) * 16);
                cp_async16(dl, gsrc_l + (size_t)(ks + 1) * 16);
                cp_commit();
                load_afrag(AH2, AL2, ks + 1, lane, warp_m, a1h, a1l);
            }
            mma_step(acc, a0h, a0l, &sB[buf][0][0][0], &sB[buf][1][0][0], warp_n, lane);
            if (has) { cp_wait0(); __syncthreads(); buf ^= 1; }
        }
        ks++;
        if (ks >= s1) break;
        {
            bool has = (ks + 1 < s1);
            if (has) {
                U32 dh = buf ? sdst_h0 : sdst_h1;
                U32 dl = buf ? sdst_l0 : sdst_l1;
                cp_async16(dh, gsrc_h + (size_t)(ks + 1) * 16);
                cp_async16(dl, gsrc_l + (size_t)(ks + 1) * 16);
                cp_commit();
                load_afrag(AH2, AL2, ks + 1, lane, warp_m, a0h, a0l);
            }
            mma_step(acc, a1h, a1l, &sB[buf][0][0][0], &sB[buf][1][0][0], warp_n, lane);
            if (has) { cp_wait0(); __syncthreads(); buf ^= 1; }
        }
        ks++;
    }

    float* Cz = C + (size_t)z * BSZ * ldc;
#pragma unroll
    for (int i = 0; i < 2; i++) {
        int m0 = warp_m * 32 + i * 16 + (lane >> 2);
#pragma unroll
        for (int j = 0; j < 8; j++) {
            int n = n0 + warp_n * 64 + j * 8 + 2 * (lane & 3);
            if (n < Nmax) {
                Cz[(size_t)m0 * ldc + n]       = acc[i][j][0];
                Cz[(size_t)(m0 + 8) * ldc + n] = acc[i][j][2];
            }
            if (n + 1 < Nmax) {
                Cz[(size_t)m0 * ldc + n + 1]       = acc[i][j][1];
                Cz[(size_t)(m0 + 8) * ldc + n + 1] = acc[i][j][3];
            }
        }
    }
}

// ---------------- transpose + bf16 hi/lo split ----------------
__global__ void k_transpose_split(const float* __restrict__ src, int K, int ncols,
                                  __nv_bfloat16* __restrict__ dh, __nv_bfloat16* __restrict__ dl)
{
    __shared__ float tile[32][33];
    int kb = blockIdx.x * 32, nb = blockIdx.y * 32;
    int tx = threadIdx.x, ty = threadIdx.y;
#pragma unroll
    for (int r = 0; r < 4; r++) {
        int k = kb + ty + 8 * r, n = nb + tx;
        tile[ty + 8 * r][tx] = (n < ncols) ? src[(size_t)k * ncols + n] : 0.0f;
    }
    __syncthreads();
#pragma unroll
    for (int r = 0; r < 4; r++) {
        int n = nb + ty + 8 * r, k = kb + tx;
        float v = tile[tx][ty + 8 * r];
        __nv_bfloat16 h = __float2bfloat16(v);
        __nv_bfloat16 l = __float2bfloat16(v - __bfloat162float(h));
        dh[(size_t)n * K + k] = h;
        dl[(size_t)n * K + k] = l;
    }
}

// ---------------- fused init ----------------
__global__ void k_init_all(const float* __restrict__ x, const float* __restrict__ strc,
                           const float* __restrict__ sas, const float* __restrict__ w1,
                           const float* __restrict__ w2) {
    long long idx = blockIdx.x * 256LL + threadIdx.x;
    if (idx < R1) {
        int i = (int)idx;
        g_xT[i] = x[(i & 127) * DIN + (i >> 7)];
        return;
    }
    idx -= R1;
    if (idx < R2) {
        int i = (int)idx;
        int d = (i >> 7) & (DMODEL - 1);
        int m = i >> 18;
        g_trace[i] = strc[d * MEMN + m];
        return;
    }
    idx -= R2;
    if (idx < R3) {
        int i = (int)idx;
        int d = i >> 7, b = i & 127;
        float v = sas[d];
        g_actT[i] = v;
        hl_store(v, d, b, g_actH2, g_actL2);
        return;
    }
    idx -= R3;
    if (idx < R4) {
        int i = (int)idx;
        int d = i & (DMODEL - 1);
        int rem = i >> 11;
        int h = rem & 63, m = rem >> 6;
        g_w1i[((d * MEMN + m) * 32 + (h & 31)) * 2 + (h >> 5)] = w1[i];
        return;
    }
    idx -= R4;
    if (idx < R5) {
        int i = (int)idx;
        g_w2T[(i & (DMODEL - 1)) * 64 + (i >> 11)] = w2[i];
    }
}

__global__ void k_init_alpha(const float* __restrict__ sas, const float* __restrict__ decay,
                             const int* __restrict__ il, const int* __restrict__ ir) {
    int p = blockIdx.x, b = threadIdx.x;
    float pf = (float)p;
    int i = (int)floorf(256.5f - sqrtf(256.5f * 256.5f - 2.0f * pf));
    if (i < 0) i = 0;
    if (i > NSY - 1) i = NSY - 1;
    while (i > 0 && (i * NSY - i * (i - 1) / 2) > p) i--;
    while (i < NSY - 1 && ((i + 1) * NSY - (i + 1) * i / 2) <= p) i++;
    int j = i + (p - (i * NSY - i * (i - 1) / 2));
    if (b == 0) {
        g_pi[p] = i; g_pj[p] = j;
        g_r[p] = expf(-fminf(fmaxf(decay[p], 0.0f), 15.0f));
    }
    g_alpha[p * BSZ + b] = sas[il[i]] * sas[ir[j]];
}

// ---------------- FMA2 GEMM (one-time z0 = x @ W_top, exact fp32) ----------------
__global__ __launch_bounds__(256) void k_gemm_f2(
    const float* __restrict__ A, const float* __restrict__ B,
    int ldb, int nkb, float* __restrict__ C, int ldc)
{
    __shared__ float As[2][8][128];
    __shared__ float Bs[2][8][128];
    int n0 = blockIdx.x * 128;
    int tid = threadIdx.x;
    int lr = tid >> 5, lc = (tid & 31) * 4;
    int ty = tid >> 4, tx = tid & 15;
    ULL acc[8][4];
#pragma unroll
    for (int i = 0; i < 8; i++)
#pragma unroll
        for (int j = 0; j < 4; j++) acc[i][j] = 0ULL;
    float4 pa = *(const float4*)(A + lr * BSZ + lc);
    float4 pb = *(const float4*)(B + (size_t)lr * ldb + n0 + lc);
    *(float4*)&As[0][lr][lc] = pa;
    *(float4*)&Bs[0][lr][lc] = pb;
    __syncthreads();
    int buf = 0;
    for (int kb = 0; kb < nkb; kb++) {
        bool has = (kb + 1 < nkb);
        if (has) {
            int krow = (kb + 1) * 8 + lr;
            pa = *(const float4*)(A + krow * BSZ + lc);
            pb = *(const float4*)(B + (size_t)krow * ldb + n0 + lc);
        }
#pragma unroll
        for (int kk = 0; kk < 8; kk++) {
            float a[8];
            *(float4*)&a[0] = *(const float4*)&As[buf][kk][ty * 8];
            *(float4*)&a[4] = *(const float4*)&As[buf][kk][ty * 8 + 4];
            ULL bv[4];
            const ULL* bp = (const ULL*)&Bs[buf][kk][tx * 8];
#pragma unroll
            for (int j = 0; j < 4; j++) bv[j] = bp[j];
#pragma unroll
            for (int i = 0; i < 8; i++) {
                ULL ad = dup2(a[i]);
#pragma unroll
                for (int j = 0; j < 4; j++) fma2(acc[i][j], ad, bv[j]);
            }
        }
        if (has) {
            *(float4*)&As[buf ^ 1][lr][lc] = pa;
            *(float4*)&Bs[buf ^ 1][lr][lc] = pb;
            __syncthreads();
            buf ^= 1;
        }
    }
#pragma unroll
    for (int i = 0; i < 8; i++) {
        int m = ty * 8 + i;
#pragma unroll
        for (int j = 0; j < 4; j++) {
            int n = n0 + tx * 8 + 2 * j;
            C[(size_t)m * ldc + n]     = lo32(acc[i][j]);
            C[(size_t)m * ldc + n + 1] = hi32(acc[i][j]);
        }
    }
}

// ---------------- GLU + LayerNorm -> trace slot ----------------
__global__ __launch_bounds__(256) void k_glu_ln(const float* __restrict__ syn_b,
                                                const float* __restrict__ ln_g,
                                                const float* __restrict__ ln_b, int slot) {
    int b = blockIdx.x, tid = threadIdx.x;
    __shared__ float sv[DMODEL];
    __shared__ float red[256];
    float s1 = 0.f, s2 = 0.f;
    for (int d = tid; d < DMODEL; d += 256) {
        float za = syn_b[d] + g_z0[b * N1 + d];
        float zb = syn_b[d + DMODEL] + g_z0[b * N1 + DMODEL + d];
#pragma unroll
        for (int s = 0; s < SK1; s++) {
            za += g_zp[(s * BSZ + b) * N1 + d];
            zb += g_zp[(s * BSZ + b) * N1 + DMODEL + d];
        }
        float v = za * sigmoidf_(zb);
        sv[d] = v; s1 += v; s2 += v * v;
    }
    red[tid] = s1; __syncthreads();
    for (int s = 128; s > 0; s >>= 1) { if (tid < s) red[tid] += red[tid + s]; __syncthreads(); }
    float mu = red[0] / (float)DMODEL;
    __syncthreads();
    red[tid] = s2; __syncthreads();
    for (int s = 128; s > 0; s >>= 1) { if (tid < s) red[tid] += red[tid + s]; __syncthreads(); }
    float inv = rsqrtf(red[0] / (float)DMODEL - mu * mu + 1e-5f);
    for (int d = tid; d < DMODEL; d += 256)
        g_trace[(slot * DMODEL + d) * BSZ + b] = (sv[d] - mu) * inv * ln_g[d] + ln_b[d];
}

// ---------------- trace_proc ----------------
__global__ __launch_bounds__(128) void k_traceproc(const float* __restrict__ b1,
                                                   const float* __restrict__ b2, int t) {
    int d = blockIdx.x, b = threadIdx.x;
    __shared__ float ws[MEMN * 64];
    const float* src = g_w1i + d * (MEMN * 64);
    for (int i = b; i < MEMN * 64; i += 128) ws[i] = src[i];
    __syncthreads();
    ULL trp[MEMN];
    int base = (t + 1) % MEMN;
#pragma unroll
    for (int m = 0; m < MEMN; m++) {
        int pm = base + m; if (pm >= MEMN) pm -= MEMN;
        trp[m] = dup2(g_trace[(pm * DMODEL + d) * BSZ + b]);
    }
    const float* b1d = b1 + d * 64;
    const float* w2d = g_w2T + d * 64;
    float o0 = b2[d * 2], o1 = b2[d * 2 + 1];
#pragma unroll
    for (int h2 = 0; h2 < 32; h2 += 2) {
        ULL acc0 = pack2(b1d[h2],     b1d[h2 + 32]);
        ULL acc1 = pack2(b1d[h2 + 1], b1d[h2 + 33]);
        const ULL* wp = ((const ULL*)ws) + h2;
#pragma unroll
        for (int m = 0; m < MEMN; m++) {
            fma2(acc0, trp[m], wp[m * 32]);
            fma2(acc1, trp[m], wp[m * 32 + 1]);
        }
        float h0 = lo32(acc0) * sigmoidf_(hi32(acc0));
        float h1 = lo32(acc1) * sigmoidf_(hi32(acc1));
        o0 += h0 * w2d[h2 * 2]     + h1 * w2d[(h2 + 1) * 2];
        o1 += h0 * w2d[h2 * 2 + 1] + h1 * w2d[(h2 + 1) * 2 + 1];
    }
    float act = o0 * sigmoidf_(o1);
    g_actT[d * BSZ + b] = act;
    hl_store(act, d, b, g_actH2, g_actL2);
}

// ---------------- pairwise + alpha + sync ----------------
__global__ __launch_bounds__(256) void k_syncpair(const int* __restrict__ il,
                                                  const int* __restrict__ ir, int t) {
    int p = blockIdx.x * 2 + threadIdx.y;
    int b = threadIdx.x;
    float l  = g_actT[il[g_pi[p]] * BSZ + b];
    float rr = g_actT[ir[g_pj[p]] * BSZ + b];
    float r = g_r[p];
    float a = r * g_alpha[p * BSZ + b] + l * rr;
    g_alpha[p * BSZ + b] = a;
    float beta = 1.0f;
    for (int k = 0; k <= t; k++) beta = r * beta + 1.0f;
    float s = a / sqrtf(beta);
    hl_store(s, p, b, g_syncH2, g_syncL2);
}

// ---------------- reduce + bias + preds + entropy ----------------
__global__ __launch_bounds__(256) void k_finish(const float* __restrict__ outb,
                                                float* __restrict__ dout, int t) {
    int b = blockIdx.x, tid = threadIdx.x;
    __shared__ float sp[OUTD];
    __shared__ float red[256];
    for (int n = tid; n < OUTD; n += 256) {
        float v = outb[n];
#pragma unroll
        for (int s = 0; s < SK2; s++) v += g_part[(s * BSZ + b) * OUTD + n];
        sp[n] = v;
        dout[(b * OUTD + n) * NITER + t] = v;
    }
    __syncthreads();
    float mx = -3.4e38f;
    for (int n = tid; n < OUTD; n += 256) mx = fmaxf(mx, sp[n]);
    red[tid] = mx; __syncthreads();
    for (int s = 128; s > 0; s >>= 1) { if (tid < s) red[tid] = fmaxf(red[tid], red[tid + s]); __syncthreads(); }
    float smax = red[0];
    __syncthreads();
    float se = 0.f;
    for (int n = tid; n < OUTD; n += 256) se += expf(sp[n] - smax);
    red[tid] = se; __syncthreads();
    for (int s = 128; s > 0; s >>= 1) { if (tid < s) red[tid] += red[tid + s]; __syncthreads(); }
    float lse = smax + logf(red[0]);
    __syncthreads();
    float ent = 0.f;
    for (int n = tid; n < OUTD; n += 256) { float lp = sp[n] - lse; ent += expf(lp) * lp; }
    red[tid] = ent; __syncthreads();
    for (int s = 128; s > 0; s >>= 1) { if (tid < s) red[tid] += red[tid + s]; __syncthreads(); }
    if (tid == 0) {
        float ne = -red[0] / logf(1000.0f);
        dout[CERT_OFF + (b * 2 + 0) * NITER + t] = ne;
        dout[CERT_OFF + (b * 2 + 1) * NITER + t] = 1.0f - ne;
    }
}

// ---------------- host ----------------
extern "C" void kernel_launch(void* const* d_in, const int* in_sizes, int n_in,
                              void* d_out, int out_size) {
    const float* x      = (const float*)d_in[0];
    const float* syn_w  = (const float*)d_in[1];
    const float* syn_b  = (const float*)d_in[2];
    const float* ln_g   = (const float*)d_in[3];
    const float* ln_b   = (const float*)d_in[4];
    const float* tp_w1  = (const float*)d_in[5];
    const float* tp_b1  = (const float*)d_in[6];
    const float* tp_w2  = (const float*)d_in[7];
    const float* tp_b2  = (const float*)d_in[8];
    const float* sas    = (const float*)d_in[9];
    const float* strc   = (const float*)d_in[10];
    const float* decay  = (const float*)d_in[11];
    const float* out_w  = (const float*)d_in[12];
    const float* out_b  = (const float*)d_in[13];
    const int*   il     = (const int*)d_in[14];
    const int*   ir     = (const int*)d_in[15];
    float* out = (float*)d_out;

    float *p_xT, *p_z0, *p_zp, *p_part;
    U32 *p_actH2, *p_actL2, *p_syncH2, *p_syncL2;
    __nv_bfloat16 *p_synTh, *p_synTl, *p_outTh, *p_outTl;
    cudaGetSymbolAddress((void**)&p_xT,     g_xT);
    cudaGetSymbolAddress((void**)&p_z0,     g_z0);
    cudaGetSymbolAddress((void**)&p_zp,     g_zp);
    cudaGetSymbolAddress((void**)&p_part,   g_part);
    cudaGetSymbolAddress((void**)&p_actH2,  g_actH2);
    cudaGetSymbolAddress((void**)&p_actL2,  g_actL2);
    cudaGetSymbolAddress((void**)&p_syncH2, g_syncH2);
    cudaGetSymbolAddress((void**)&p_syncL2, g_syncL2);
    cudaGetSymbolAddress((void**)&p_synTh,  g_synTh);
    cudaGetSymbolAddress((void**)&p_synTl,  g_synTl);
    cudaGetSymbolAddress((void**)&p_outTh,  g_outTh);
    cudaGetSymbolAddress((void**)&p_outTl,  g_outTl);

    // launch order: the first k_gemm_mma is launch #4 (ncu window target)
    k_init_all<<<RTOT / 256, 256>>>(x, strc, sas, tp_w1, tp_w2);
    k_transpose_split<<<dim3(DMODEL / 32, N1 / 32), dim3(32, 8)>>>(
        syn_w + (size_t)DIN * N1, DMODEL, N1, p_synTh, p_synTl);
    k_transpose_split<<<dim3(NSYNC / 32, OUTPAD / 32), dim3(32, 8)>>>(
        out_w, NSYNC, OUTD, p_outTh, p_outTl);

    for (int t = 0; t < NITER; t++) {
        k_gemm_mma<<<dim3(N1 / 128, SK1), 256>>>(p_actH2, p_actL2, p_synTh, p_synTl,
                                                 DMODEL, N1, DMODEL / 16, SK1, p_zp, N1);
        if (t == 0) {
            k_gemm_f2<<<N1 / 128, 256>>>(p_xT, syn_w, N1, DIN / 8, p_z0, N1);
            k_init_alpha<<<NSYNC, BSZ>>>(sas, decay, il, ir);
        }
        k_glu_ln<<<BSZ, 256>>>(syn_b, ln_g, ln_b, t % MEMN);
        k_traceproc<<<DMODEL, BSZ>>>(tp_b1, tp_b2, t);
        k_syncpair<<<NSYNC / 2, dim3(BSZ, 2)>>>(il, ir, t);
        k_gemm_mma<<<dim3(OUTPAD / 128, SK2), 256>>>(p_syncH2, p_syncL2, p_outTh, p_outTl,
                                                     NSYNC, OUTD, NSYNC / 16, SK2, p_part, OUTD);
        k_finish<<<BSZ, 256>>>(out_b, out, t);
    }
}